// round 11
// baseline (speedup 1.0000x reference)
#include <cuda_runtime.h>

// GCN: out = spmm(w, relu(spmm(w, x@W1^T) + b1) @ W2^T) + b2
// using the commutation spmm(h)@W^T == spmm(h@W^T).
//
// Round 11: feature-chunked tail overlap.
//   spmm1 and gemm2 are feature-separable (relu elementwise; y2 sums over
//   feature chunks), so split 128 feats into 2x64:
//     spmm64(ch0) -> gemm2ch<ch0,overwrite> on side stream, overlapped with
//     spmm64(ch1) on main; then gemm2ch<ch1,accumulate>; then spmm40.
//   Tail 155us -> ~138us. CSR build fork (round 10) unchanged.

#define NMAX 100000
#define EMAX 1600000
#define SCAN_CHUNK 1024
#define SCAN_NB ((NMAX + SCAN_CHUNK - 1) / SCAN_CHUNK)

__device__ int   g_is64;
__device__ __align__(16) float g_deg[NMAX];   // degree, then dinv (in place)
__device__ __align__(16) int   g_cnt[NMAX];
__device__ int   g_rowptr[NMAX + 1];
__device__ int   g_cursor[NMAX];
__device__ int   g_bsum[128];
__device__ int   g_boff[128];
__device__ __align__(16) int2  g_cw[EMAX];    // {col, __float_as_int(w)}
__device__ __align__(16) float g_y1[(size_t)NMAX * 128];
__device__ __align__(16) float g_h [(size_t)NMAX * 128];
__device__ __align__(16) float g_y2[(size_t)NMAX * 40];

// read edge index e from row (part==0) or col (part==1) stream
__device__ __forceinline__ int edge_at(const void* ei, int E, int part, int e,
                                       int is64) {
    if (is64) return (int)((const long long*)ei)[(size_t)part * E + e];
    return ((const int*)ei)[(size_t)part * E + e];
}

// ------------------------------------------ zero + dtype detect (merged)
__global__ void k_zero(const void* ei, int E, int n) {
    int i = blockIdx.x * blockDim.x + threadIdx.x;
    if (i < n) { g_deg[i] = 0.0f; g_cnt[i] = 0; }
    if (i == 0) {
        const long long* p = (const long long*)ei;
        int ok = 1;
        int m = (E < 8) ? E : 8;
        for (int j = 0; j < m; j++) {
            long long v = p[j];
            if (v < 0 || v >= NMAX) ok = 0;
        }
        g_is64 = ok;
    }
}

// ------------------------------------------------------- degree + count
__global__ void k_deg_count(const void* __restrict__ ei,
                            const float* __restrict__ cv, int E) {
    int e = blockIdx.x * blockDim.x + threadIdx.x;
    if (e >= E) return;
    int is64 = g_is64;
    int r = edge_at(ei, E, 0, e, is64);
    atomicAdd(&g_deg[r], cv[e]);
    atomicAdd(&g_cnt[r], 1);
}

// ------------------------------------- scan pass 1: block sums (+ dinv)
__global__ void k_scan1(int n) {
    __shared__ int wsum[8];
    int b = blockIdx.x, t = threadIdx.x;
    int base = b * SCAN_CHUNK + t * 4;

    int4 v = make_int4(0, 0, 0, 0);
    if (base + 3 < n)      v = *(const int4*)&g_cnt[base];
    else if (base < n) {
        v.x = g_cnt[base];
        if (base + 1 < n) v.y = g_cnt[base + 1];
        if (base + 2 < n) v.z = g_cnt[base + 2];
    }
    int s = v.x + v.y + v.z + v.w;

    int lane = t & 31, w = t >> 5;
    int inc = s;
    #pragma unroll
    for (int o = 1; o < 32; o <<= 1) {
        int tv = __shfl_up_sync(0xFFFFFFFFu, inc, o);
        if (lane >= o) inc += tv;
    }
    if (lane == 31) wsum[w] = inc;
    __syncthreads();
    if (t == 0) {
        int tot = 0;
        #pragma unroll
        for (int j = 0; j < 8; j++) tot += wsum[j];
        g_bsum[b] = tot;
    }

    if (base + 3 < n) {
        float4 d = *(const float4*)&g_deg[base];
        d.x = (d.x > 0.f) ? rsqrtf(d.x) : 0.f;
        d.y = (d.y > 0.f) ? rsqrtf(d.y) : 0.f;
        d.z = (d.z > 0.f) ? rsqrtf(d.z) : 0.f;
        d.w = (d.w > 0.f) ? rsqrtf(d.w) : 0.f;
        *(float4*)&g_deg[base] = d;
    } else {
        for (int j = 0; j < 4 && base + j < n; j++) {
            float d = g_deg[base + j];
            g_deg[base + j] = (d > 0.f) ? rsqrtf(d) : 0.f;
        }
    }
}

// ---------------------------- scan pass 2: exclusive scan of block sums
__global__ void k_scan2(int nb, int n) {
    __shared__ int wtot[4];
    int t = threadIdx.x;
    int v = (t < nb) ? g_bsum[t] : 0;
    int lane = t & 31, w = t >> 5;
    int inc = v;
    #pragma unroll
    for (int o = 1; o < 32; o <<= 1) {
        int tv = __shfl_up_sync(0xFFFFFFFFu, inc, o);
        if (lane >= o) inc += tv;
    }
    if (lane == 31) wtot[w] = inc;
    __syncthreads();
    int woff = 0;
    #pragma unroll
    for (int j = 0; j < 4; j++) if (j < w) woff += wtot[j];
    int excl = woff + inc - v;
    if (t < nb) g_boff[t] = excl;
    if (t == 127) g_rowptr[n] = woff + inc;
}

// ------------------------- scan pass 3: propagate, write rowptr + cursor
__global__ void k_scan3(int n) {
    __shared__ int wsum[8];
    int b = blockIdx.x, t = threadIdx.x;
    int base = b * SCAN_CHUNK + t * 4;

    int4 v = make_int4(0, 0, 0, 0);
    if (base + 3 < n)      v = *(const int4*)&g_cnt[base];
    else if (base < n) {
        v.x = g_cnt[base];
        if (base + 1 < n) v.y = g_cnt[base + 1];
        if (base + 2 < n) v.z = g_cnt[base + 2];
    }
    int s = v.x + v.y + v.z + v.w;

    int lane = t & 31, w = t >> 5;
    int inc = s;
    #pragma unroll
    for (int o = 1; o < 32; o <<= 1) {
        int tv = __shfl_up_sync(0xFFFFFFFFu, inc, o);
        if (lane >= o) inc += tv;
    }
    if (lane == 31) wsum[w] = inc;
    __syncthreads();
    int woff = 0;
    #pragma unroll
    for (int j = 0; j < 8; j++) if (j < w) woff += wsum[j];

    int excl = g_boff[b] + woff + inc - s;
    if (base < n) {
        int p0 = excl, p1 = p0 + v.x, p2 = p1 + v.y, p3 = p2 + v.z;
        g_rowptr[base] = p0;  g_cursor[base] = p0;
        if (base + 1 < n) { g_rowptr[base + 1] = p1; g_cursor[base + 1] = p1; }
        if (base + 2 < n) { g_rowptr[base + 2] = p2; g_cursor[base + 2] = p2; }
        if (base + 3 < n) { g_rowptr[base + 3] = p3; g_cursor[base + 3] = p3; }
    }
}

// -------------------------------------------------------- CSR scatter + w
__global__ void k_scatter(const void* __restrict__ ei,
                          const float* __restrict__ cv, int E) {
    int e = blockIdx.x * blockDim.x + threadIdx.x;
    if (e >= E) return;
    int is64 = g_is64;
    int r = edge_at(ei, E, 0, e, is64);
    int c = edge_at(ei, E, 1, e, is64);
    float wv = g_deg[r] * cv[e] * g_deg[c];
    int pos = atomicAdd(&g_cursor[r], 1);
    g_cw[pos] = make_int2(c, __float_as_int(wv));
}

// ------------------------------------------------- GEMM1 (full 128 cols)
// y1[n,c] = sum_k x[n,k] * W1[c,k].  64 nodes x 256 threads, warp=8 nodes,
// lane = cols lane+32j (j<4). W k-chunked, stride 17 (conflict-free).
__global__ void k_gemm1(const float* __restrict__ X,
                        const float* __restrict__ W, int N) {
    __shared__ float xs[64 * 128];
    __shared__ float ws[4 * 32 * 17];

    int tid = threadIdx.x;
    int nb = blockIdx.x * 64;

    for (int i = tid; i < 64 * 128; i += 256) {
        int n = i >> 7;
        xs[i] = (nb + n < N) ? X[(size_t)nb * 128 + i] : 0.0f;
    }

    int lane = tid & 31, wid = tid >> 5;
    float acc[8][4];
    #pragma unroll
    for (int i = 0; i < 8; i++)
        #pragma unroll
        for (int j = 0; j < 4; j++) acc[i][j] = 0.0f;

    for (int kb = 0; kb < 128; kb += 16) {
        __syncthreads();
        for (int i = tid; i < 4 * 32 * 16; i += 256) {
            int hh = i >> 4, kk = i & 15;
            ws[hh * 17 + kk] = W[(size_t)hh * 128 + kb + kk];
        }
        __syncthreads();

        #pragma unroll
        for (int kk = 0; kk < 16; kk++) {
            float wf[4];
            #pragma unroll
            for (int j = 0; j < 4; j++) wf[j] = ws[(lane + 32 * j) * 17 + kk];
            #pragma unroll
            for (int i = 0; i < 8; i++) {
                float xf = xs[(wid * 8 + i) * 128 + kb + kk];
                #pragma unroll
                for (int j = 0; j < 4; j++)
                    acc[i][j] = fmaf(xf, wf[j], acc[i][j]);
            }
        }
    }

    #pragma unroll
    for (int i = 0; i < 8; i++) {
        int n = nb + wid * 8 + i;
        if (n < N) {
            #pragma unroll
            for (int j = 0; j < 4; j++)
                g_y1[(size_t)n * 128 + lane + 32 * j] = acc[i][j];
        }
    }
}

// ----------------------- CSR SpMM over a 64-feature chunk, bias + relu
// reads g_y1[:, ch*64 : ch*64+64], writes g_h same cols. warp=row, float2.
__global__ void k_spmm64(const float* __restrict__ bias, int N, int ch) {
    int wid = threadIdx.x >> 5, lane = threadIdx.x & 31;
    int r = blockIdx.x * 8 + wid;
    if (r >= N) return;
    int fo = ch * 64 + 2 * lane;
    int e0 = g_rowptr[r], e1 = g_rowptr[r + 1];
    float2 acc = make_float2(0.f, 0.f);
    for (int e = e0; e < e1; e++) {
        int2 cw = g_cw[e];
        float wv = __int_as_float(cw.y);
        float2 v = *(const float2*)&g_y1[(size_t)cw.x * 128 + fo];
        acc.x = fmaf(wv, v.x, acc.x);
        acc.y = fmaf(wv, v.y, acc.y);
    }
    float2 b = *(const float2*)&bias[fo];
    acc.x = fmaxf(acc.x + b.x, 0.f);
    acc.y = fmaxf(acc.y + b.y, 0.f);
    *(float2*)&g_h[(size_t)r * 128 + fo] = acc;
}

// ------------------- GEMM2 over one 64-k chunk: y2 (+)= h_chunk @ W2ch^T
// 64 nodes x 256 threads, warp=8 nodes, lane = cols lane, lane+32 (40 real).
template <int ACC>
__global__ void k_gemm2ch(const float* __restrict__ W2, int N, int ch) {
    __shared__ float xs[64 * 64];
    __shared__ float ws[64 * 17];

    int tid = threadIdx.x;
    int nb = blockIdx.x * 64;
    int ko = ch * 64;

    // fill xs: 64 rows x 64 k (chunk), float4 loads
    for (int i = tid; i < 64 * 16; i += 256) {
        int n = i >> 4, q = i & 15;
        ((float4*)xs)[i] = (nb + n < N)
            ? ((const float4*)(g_h + (size_t)(nb + n) * 128 + ko))[q]
            : make_float4(0.f, 0.f, 0.f, 0.f);
    }

    int lane = tid & 31, wid = tid >> 5;
    float acc[8][2];
    #pragma unroll
    for (int i = 0; i < 8; i++) { acc[i][0] = 0.f; acc[i][1] = 0.f; }

    for (int kb = 0; kb < 64; kb += 16) {
        __syncthreads();
        for (int i = tid; i < 64 * 16; i += 256) {
            int hh = i >> 4, kk = i & 15;
            ws[hh * 17 + kk] = (hh < 40) ? W2[(size_t)hh * 128 + ko + kb + kk]
                                         : 0.0f;
        }
        __syncthreads();

        #pragma unroll
        for (int kk = 0; kk < 16; kk++) {
            float w0 = ws[lane * 17 + kk];
            float w1 = ws[(lane + 32) * 17 + kk];
            #pragma unroll
            for (int i = 0; i < 8; i++) {
                float xf = xs[(wid * 8 + i) * 64 + kb + kk];
                acc[i][0] = fmaf(xf, w0, acc[i][0]);
                acc[i][1] = fmaf(xf, w1, acc[i][1]);
            }
        }
    }

    #pragma unroll
    for (int i = 0; i < 8; i++) {
        int n = nb + wid * 8 + i;
        if (n < N) {
            float* yr = g_y2 + (size_t)n * 40;
            if (lane < 40) {
                if (ACC) yr[lane] += acc[i][0]; else yr[lane] = acc[i][0];
            }
            if (lane + 32 < 40) {
                if (ACC) yr[lane + 32] += acc[i][1];
                else     yr[lane + 32]  = acc[i][1];
            }
        }
    }
}

// -------------------------------------------- CSR SpMM, 40 feats, + bias
__global__ void k_spmm40(const float* __restrict__ bias,
                         float* __restrict__ out, int N) {
    int wid = threadIdx.x >> 5, lane = threadIdx.x & 31;
    int r = blockIdx.x * 8 + wid;
    if (r >= N) return;
    int e0 = g_rowptr[r], e1 = g_rowptr[r + 1];
    float a0 = 0.f, a1 = 0.f;
    for (int e = e0; e < e1; e++) {
        int2 cw = g_cw[e];
        float wv = __int_as_float(cw.y);
        const float* f = g_y2 + (size_t)cw.x * 40;
        a0 = fmaf(wv, f[lane], a0);
        if (lane < 8) a1 = fmaf(wv, f[32 + lane], a1);
    }
    out[(size_t)r * 40 + lane] = a0 + bias[lane];
    if (lane < 8) out[(size_t)r * 40 + 32 + lane] = a1 + bias[32 + lane];
}

// ----------------------------------------------------------------- host
extern "C" void kernel_launch(void* const* d_in, const int* in_sizes, int n_in,
                              void* d_out, int out_size) {
    const float* x  = (const float*)d_in[0];
    const void*  ei = d_in[1];                 // int32 or int64, detected
    const float* cv = (const float*)d_in[2];
    const float* W1 = (const float*)d_in[3];
    const float* b1 = (const float*)d_in[4];
    const float* W2 = (const float*)d_in[5];
    const float* b2 = (const float*)d_in[6];
    float* out = (float*)d_out;

    int N = in_sizes[0] / 128;
    int E = in_sizes[2];

    static cudaStream_t s1 = nullptr, s2 = nullptr;
    static cudaEvent_t ev_fork = nullptr, ev_side = nullptr;
    static cudaEvent_t ev_a = nullptr, ev_g2a = nullptr;
    if (s1 == nullptr) {
        cudaStreamCreateWithFlags(&s1, cudaStreamNonBlocking);
        cudaStreamCreateWithFlags(&s2, cudaStreamNonBlocking);
        cudaEventCreateWithFlags(&ev_fork, cudaEventDisableTiming);
        cudaEventCreateWithFlags(&ev_side, cudaEventDisableTiming);
        cudaEventCreateWithFlags(&ev_a,    cudaEventDisableTiming);
        cudaEventCreateWithFlags(&ev_g2a,  cudaEventDisableTiming);
    }

    int gn = (N + 255) / 256;
    int ge = (E + 255) / 256;
    int gb = (N + 63) / 64;
    int gs = (N + 7) / 8;
    int nbs = (N + SCAN_CHUNK - 1) / SCAN_CHUNK;

    // Fork: CSR build on s1, concurrent with GEMM1 on main.
    cudaEventRecord(ev_fork, 0);
    cudaStreamWaitEvent(s1, ev_fork, 0);

    k_zero     <<<gn, 256, 0, s1>>>(ei, E, N);
    k_deg_count<<<ge, 256, 0, s1>>>(ei, cv, E);
    k_scan1    <<<nbs, 256, 0, s1>>>(N);
    k_scan2    <<<1, 128, 0, s1>>>(nbs, N);
    k_scan3    <<<nbs, 256, 0, s1>>>(N);
    k_scatter  <<<ge, 256, 0, s1>>>(ei, cv, E);
    cudaEventRecord(ev_side, s1);

    // GEMM1 on main: y1 = x @ W1^T (independent of CSR).
    k_gemm1<<<gb, 256>>>(x, W1, N);

    // Join side chain, then chunked tail:
    cudaStreamWaitEvent(0, ev_side, 0);

    // chunk 0 spmm -> (on s2) gemm2 chunk 0, overlapped with chunk 1 spmm
    k_spmm64<<<gs, 256>>>(b1, N, 0);
    cudaEventRecord(ev_a, 0);
    cudaStreamWaitEvent(s2, ev_a, 0);
    k_gemm2ch<0><<<gb, 256, 0, s2>>>(W2, N, 0);
    cudaEventRecord(ev_g2a, s2);

    k_spmm64<<<gs, 256>>>(b1, N, 1);

    // gemm2 chunk 1 accumulates after chunk-0 gemm finished
    cudaStreamWaitEvent(0, ev_g2a, 0);
    k_gemm2ch<1><<<gb, 256>>>(W2, N, 1);

    // SpMM2 + bias -> out
    k_spmm40<<<gs, 256>>>(b2, out, N);
}

// round 13
// speedup vs baseline: 1.1802x; 1.1802x over previous
#include <cuda_runtime.h>
#include <cuda_bf16.h>

// GCN: out = spmm(w, relu(spmm(w, x@W1^T) + b1) @ W2^T) + b2
// using spmm(h)@W^T == spmm(h@W^T).
//
// Round 13 = round 12 with the host-side __device__-symbol bug fixed:
// weight-split pointers are now selected INSIDE k_gemm_mma via the LAYER
// template param (host code passing g_W1hi etc. passed the host shadow
// address -> garbage reads -> rel_err ~1.0).
//  - Both GEMMs: mma.sync.m16n8k16 bf16 hi/lo split (err ~1e-5).
//  - CSR stores raw {col, C}; dinv per-row (no float atomics); norm folded
//    into spmm loops.
//  - CSR build forked on side stream; gemm1 is the 4th launch (ncu slot).

#define NMAX 100000
#define EMAX 1600000
#define SCAN_CHUNK 1024

__device__ int   g_is64;
__device__ __align__(16) float g_deg[NMAX];          // dinv after k_rowdeg
__device__ __align__(16) int   g_cnt[NMAX];
__device__ int   g_rowptr[NMAX + 1];
__device__ int   g_cursor[NMAX];
__device__ int   g_bsum[128];
__device__ int   g_boff[128];
__device__ __align__(16) int2  g_cw[EMAX];           // {col, bits(C)}
__device__ __align__(16) float g_y1[(size_t)NMAX * 128];
__device__ __align__(16) __nv_bfloat16 g_hhi[(size_t)NMAX * 128];
__device__ __align__(16) __nv_bfloat16 g_hlo[(size_t)NMAX * 128];
__device__ __align__(16) float g_y2[(size_t)NMAX * 40];
__device__ __align__(16) __nv_bfloat16 g_W1hi[128 * 128];
__device__ __align__(16) __nv_bfloat16 g_W1lo[128 * 128];
__device__ __align__(16) __nv_bfloat16 g_W2hi[40 * 128];
__device__ __align__(16) __nv_bfloat16 g_W2lo[40 * 128];

typedef unsigned int u32;

__device__ __forceinline__ u32 pack2bf(float x, float y) {
    __nv_bfloat162 t = __floats2bfloat162_rn(x, y);
    return *reinterpret_cast<u32*>(&t);
}
__device__ __forceinline__ float bfhi(float x) {
    return __bfloat162float(__float2bfloat16_rn(x));
}
__device__ __forceinline__ void mma_bf16(float* c, u32 a0, u32 a1, u32 a2,
                                         u32 a3, u32 b0, u32 b1) {
    asm("mma.sync.aligned.m16n8k16.row.col.f32.bf16.bf16.f32 "
        "{%0,%1,%2,%3}, {%4,%5,%6,%7}, {%8,%9}, {%0,%1,%2,%3};"
        : "+f"(c[0]), "+f"(c[1]), "+f"(c[2]), "+f"(c[3])
        : "r"(a0), "r"(a1), "r"(a2), "r"(a3), "r"(b0), "r"(b1));
}

__device__ __forceinline__ int edge_at(const void* ei, int E, int part, int e,
                                       int is64) {
    if (is64) return (int)((const long long*)ei)[(size_t)part * E + e];
    return ((const int*)ei)[(size_t)part * E + e];
}

// --------------------------------------------- W split (once, tiny)
__global__ void k_wsplit(const float* __restrict__ W1,
                         const float* __restrict__ W2) {
    int i = blockIdx.x * blockDim.x + threadIdx.x;
    if (i < 128 * 128) {
        float v = W1[i], h = bfhi(v);
        g_W1hi[i] = __float2bfloat16_rn(v);
        g_W1lo[i] = __float2bfloat16_rn(v - h);
    }
    if (i < 40 * 128) {
        float v = W2[i], h = bfhi(v);
        g_W2hi[i] = __float2bfloat16_rn(v);
        g_W2lo[i] = __float2bfloat16_rn(v - h);
    }
}

// --------------------------------------------- zero counts + dtype detect
__global__ void k_zero(const void* ei, int E, int n) {
    int i = blockIdx.x * blockDim.x + threadIdx.x;
    if (i < n) g_cnt[i] = 0;
    if (i == 0) {
        const long long* p = (const long long*)ei;
        int ok = 1;
        int m = (E < 8) ? E : 8;
        for (int j = 0; j < m; j++) {
            long long v = p[j];
            if (v < 0 || v >= NMAX) ok = 0;
        }
        g_is64 = ok;
    }
}

// --------------------------------------------------------- row counts
__global__ void k_cnt(const void* __restrict__ ei, int E) {
    int e = blockIdx.x * blockDim.x + threadIdx.x;
    if (e >= E) return;
    atomicAdd(&g_cnt[edge_at(ei, E, 0, e, g_is64)], 1);
}

// ------------------------------------- scan pass 1: block sums
__global__ void k_scan1(int n) {
    __shared__ int wsum[8];
    int b = blockIdx.x, t = threadIdx.x;
    int base = b * SCAN_CHUNK + t * 4;
    int4 v = make_int4(0, 0, 0, 0);
    if (base + 3 < n)      v = *(const int4*)&g_cnt[base];
    else if (base < n) {
        v.x = g_cnt[base];
        if (base + 1 < n) v.y = g_cnt[base + 1];
        if (base + 2 < n) v.z = g_cnt[base + 2];
    }
    int s = v.x + v.y + v.z + v.w;
    int lane = t & 31, w = t >> 5;
    int inc = s;
    #pragma unroll
    for (int o = 1; o < 32; o <<= 1) {
        int tv = __shfl_up_sync(0xFFFFFFFFu, inc, o);
        if (lane >= o) inc += tv;
    }
    if (lane == 31) wsum[w] = inc;
    __syncthreads();
    if (t == 0) {
        int tot = 0;
        #pragma unroll
        for (int j = 0; j < 8; j++) tot += wsum[j];
        g_bsum[b] = tot;
    }
}

// ---------------------------- scan pass 2: scan of block sums
__global__ void k_scan2(int nb, int n) {
    __shared__ int wtot[4];
    int t = threadIdx.x;
    int v = (t < nb) ? g_bsum[t] : 0;
    int lane = t & 31, w = t >> 5;
    int inc = v;
    #pragma unroll
    for (int o = 1; o < 32; o <<= 1) {
        int tv = __shfl_up_sync(0xFFFFFFFFu, inc, o);
        if (lane >= o) inc += tv;
    }
    if (lane == 31) wtot[w] = inc;
    __syncthreads();
    int woff = 0;
    #pragma unroll
    for (int j = 0; j < 4; j++) if (j < w) woff += wtot[j];
    int excl = woff + inc - v;
    if (t < nb) g_boff[t] = excl;
    if (t == 127) g_rowptr[n] = woff + inc;
}

// ------------------------- scan pass 3: write rowptr + cursor
__global__ void k_scan3(int n) {
    __shared__ int wsum[8];
    int b = blockIdx.x, t = threadIdx.x;
    int base = b * SCAN_CHUNK + t * 4;
    int4 v = make_int4(0, 0, 0, 0);
    if (base + 3 < n)      v = *(const int4*)&g_cnt[base];
    else if (base < n) {
        v.x = g_cnt[base];
        if (base + 1 < n) v.y = g_cnt[base + 1];
        if (base + 2 < n) v.z = g_cnt[base + 2];
    }
    int s = v.x + v.y + v.z + v.w;
    int lane = t & 31, w = t >> 5;
    int inc = s;
    #pragma unroll
    for (int o = 1; o < 32; o <<= 1) {
        int tv = __shfl_up_sync(0xFFFFFFFFu, inc, o);
        if (lane >= o) inc += tv;
    }
    if (lane == 31) wsum[w] = inc;
    __syncthreads();
    int woff = 0;
    #pragma unroll
    for (int j = 0; j < 8; j++) if (j < w) woff += wsum[j];
    int excl = g_boff[b] + woff + inc - s;
    if (base < n) {
        int p0 = excl, p1 = p0 + v.x, p2 = p1 + v.y, p3 = p2 + v.z;
        g_rowptr[base] = p0;  g_cursor[base] = p0;
        if (base + 1 < n) { g_rowptr[base + 1] = p1; g_cursor[base + 1] = p1; }
        if (base + 2 < n) { g_rowptr[base + 2] = p2; g_cursor[base + 2] = p2; }
        if (base + 3 < n) { g_rowptr[base + 3] = p3; g_cursor[base + 3] = p3; }
    }
}

// ------------------------------------- CSR scatter: raw {col, C}
__global__ void k_scatter(const void* __restrict__ ei,
                          const float* __restrict__ cv, int E) {
    int e = blockIdx.x * blockDim.x + threadIdx.x;
    if (e >= E) return;
    int is64 = g_is64;
    int r = edge_at(ei, E, 0, e, is64);
    int c = edge_at(ei, E, 1, e, is64);
    int pos = atomicAdd(&g_cursor[r], 1);
    g_cw[pos] = make_int2(c, __float_as_int(cv[e]));
}

// --------------------- per-row degree from CSR -> dinv (no atomics)
__global__ void k_rowdeg(int N) {
    int wid = threadIdx.x >> 5, lane = threadIdx.x & 31;
    int r = blockIdx.x * 8 + wid;
    if (r >= N) return;
    int e0 = g_rowptr[r], e1 = g_rowptr[r + 1];
    float s = 0.f;
    for (int e = e0 + lane; e < e1; e += 32) s += __int_as_float(g_cw[e].y);
    #pragma unroll
    for (int o = 16; o > 0; o >>= 1) s += __shfl_xor_sync(0xFFFFFFFFu, s, o);
    if (lane == 0) g_deg[r] = (s > 0.f) ? rsqrtf(s) : 0.f;
}

// ---------------------------------------------- bf16-split MMA GEMM
// Y[n,c] = sum_k X[n,k]*W[c,k], K=128. Block: 64 rows x (NCG*64) cols,
// warps = 4 rowgroups x NCG colgroups. m16n8k16 fragments staged in smem
// fragment-contiguous: As stride 9 words, Bs stride 5 words (conflict-free).
// LAYER 1: A from fp32 Xin (split inline), W = g_W1hi/lo, Y = g_y1 (128).
// LAYER 2: A from g_hhi/g_hlo, W = g_W2hi/lo, Y = g_y2 (40 of 64).
// All device-global operands resolved IN DEVICE CODE (no host symbol use).
template <int NCG, int LAYER>
__global__ void k_gemm_mma(const float* __restrict__ Xin, int N, int Hreal) {
    constexpr int NTHR = NCG * 128;
    __shared__ u32 As[4 * 32 * 9];
    __shared__ u32 Bs[NCG * 8 * 32 * 5];

    const __nv_bfloat16* Whi = (LAYER == 1) ? g_W1hi : g_W2hi;
    const __nv_bfloat16* Wlo = (LAYER == 1) ? g_W1lo : g_W2lo;

    int tid = threadIdx.x;
    int nb = blockIdx.x * 64;
    int lane = tid & 31, wid = tid >> 5;
    int rowg = wid & 3, colg = wid >> 2;

    float acc[8][4];
    #pragma unroll
    for (int j = 0; j < 8; j++)
        #pragma unroll
        for (int q = 0; q < 4; q++) acc[j][q] = 0.f;

    for (int kb = 0; kb < 128; kb += 16) {
        __syncthreads();
        // ---- fill A fragments (512 slots: rowg,lane,areg)
        for (int s = tid; s < 512; s += NTHR) {
            int rg = s >> 7, rem = s & 127, ln = rem >> 2, areg = rem & 3;
            int r = nb + rg * 16 + (ln >> 2) + ((areg & 1) ? 8 : 0);
            int k = kb + (ln & 3) * 2 + ((areg & 2) ? 8 : 0);
            u32 hi, lo;
            if (r < N) {
                if (LAYER == 1) {
                    float2 v = *(const float2*)&Xin[(size_t)r * 128 + k];
                    float hx = bfhi(v.x), hy = bfhi(v.y);
                    hi = pack2bf(v.x, v.y);
                    lo = pack2bf(v.x - hx, v.y - hy);
                } else {
                    hi = *(const u32*)&g_hhi[(size_t)r * 128 + k];
                    lo = *(const u32*)&g_hlo[(size_t)r * 128 + k];
                }
            } else { hi = 0u; lo = 0u; }
            int base = (rg * 32 + ln) * 9;
            As[base + areg]     = hi;
            As[base + 4 + areg] = lo;
        }
        // ---- fill B fragments (NCG*512 slots: ntile,lane,breg)
        for (int s = tid; s < NCG * 512; s += NTHR) {
            int nt = s >> 6, rem = s & 63, ln = rem >> 1, breg = rem & 1;
            int c = nt * 8 + (ln >> 2);
            int k = kb + (ln & 3) * 2 + breg * 8;
            u32 hi = 0u, lo = 0u;
            if (c < Hreal) {
                hi = *(const u32*)&Whi[(size_t)c * 128 + k];
                lo = *(const u32*)&Wlo[(size_t)c * 128 + k];
            }
            int base = (nt * 32 + ln) * 5;
            Bs[base + breg]     = hi;
            Bs[base + 2 + breg] = lo;
        }
        __syncthreads();

        // ---- compute
        int ab = (rowg * 32 + lane) * 9;
        u32 ah0 = As[ab], ah1 = As[ab + 1], ah2 = As[ab + 2], ah3 = As[ab + 3];
        u32 al0 = As[ab + 4], al1 = As[ab + 5], al2 = As[ab + 6], al3 = As[ab + 7];
        #pragma unroll
        for (int j = 0; j < 8; j++) {
            int bb = ((colg * 8 + j) * 32 + lane) * 5;
            u32 b0h = Bs[bb], b1h = Bs[bb + 1];
            u32 b0l = Bs[bb + 2], b1l = Bs[bb + 3];
            mma_bf16(acc[j], ah0, ah1, ah2, ah3, b0h, b1h);
            mma_bf16(acc[j], ah0, ah1, ah2, ah3, b0l, b1l);
            mma_bf16(acc[j], al0, al1, al2, al3, b0h, b1h);
        }
    }

    // ---- epilogue
    int gid = lane >> 2, tig = lane & 3;
    int r0 = nb + rowg * 16 + gid;
    int r1 = r0 + 8;
    float* Y = (LAYER == 1) ? g_y1 : g_y2;
    #pragma unroll
    for (int j = 0; j < 8; j++) {
        int c = colg * 64 + j * 8 + tig * 2;
        if (c + 1 < Hreal || LAYER == 1) {
            if (r0 < N) *(float2*)&Y[(size_t)r0 * Hreal + c] =
                make_float2(acc[j][0], acc[j][1]);
            if (r1 < N) *(float2*)&Y[(size_t)r1 * Hreal + c] =
                make_float2(acc[j][2], acc[j][3]);
        }
    }
}

// ------------------- CSR SpMM 128 feats + norm + bias + relu -> h split
__global__ void k_spmm128(const float* __restrict__ bias, int N) {
    int wid = threadIdx.x >> 5, lane = threadIdx.x & 31;
    int r = blockIdx.x * 8 + wid;
    if (r >= N) return;
    const float4* feat = (const float4*)g_y1;
    int e0 = g_rowptr[r], e1 = g_rowptr[r + 1];
    float4 acc = make_float4(0.f, 0.f, 0.f, 0.f);
    for (int e = e0; e < e1; e++) {
        int2 cw = g_cw[e];
        float wv = __int_as_float(cw.y) * g_deg[cw.x];
        float4 v = feat[(size_t)cw.x * 32 + lane];
        acc.x = fmaf(wv, v.x, acc.x);
        acc.y = fmaf(wv, v.y, acc.y);
        acc.z = fmaf(wv, v.z, acc.z);
        acc.w = fmaf(wv, v.w, acc.w);
    }
    float dr = g_deg[r];
    float4 b = ((const float4*)bias)[lane];
    acc.x = fmaxf(fmaf(dr, acc.x, b.x), 0.f);
    acc.y = fmaxf(fmaf(dr, acc.y, b.y), 0.f);
    acc.z = fmaxf(fmaf(dr, acc.z, b.z), 0.f);
    acc.w = fmaxf(fmaf(dr, acc.w, b.w), 0.f);
    // split h into bf16 hi/lo for the tensor-core GEMM2
    u32 h01 = pack2bf(acc.x, acc.y), h23 = pack2bf(acc.z, acc.w);
    u32 l01 = pack2bf(acc.x - bfhi(acc.x), acc.y - bfhi(acc.y));
    u32 l23 = pack2bf(acc.z - bfhi(acc.z), acc.w - bfhi(acc.w));
    ((uint2*)g_hhi)[(size_t)r * 32 + lane] = make_uint2(h01, h23);
    ((uint2*)g_hlo)[(size_t)r * 32 + lane] = make_uint2(l01, l23);
}

// ------------------------- CSR SpMM, 40 feats + norm + bias -> out
__global__ void k_spmm40(const float* __restrict__ bias,
                         float* __restrict__ out, int N) {
    int wid = threadIdx.x >> 5, lane = threadIdx.x & 31;
    int r = blockIdx.x * 8 + wid;
    if (r >= N) return;
    int e0 = g_rowptr[r], e1 = g_rowptr[r + 1];
    float a0 = 0.f, a1 = 0.f;
    for (int e = e0; e < e1; e++) {
        int2 cw = g_cw[e];
        float wv = __int_as_float(cw.y) * g_deg[cw.x];
        const float* f = g_y2 + (size_t)cw.x * 40;
        a0 = fmaf(wv, f[lane], a0);
        if (lane < 8) a1 = fmaf(wv, f[32 + lane], a1);
    }
    float dr = g_deg[r];
    out[(size_t)r * 40 + lane] = fmaf(dr, a0, bias[lane]);
    if (lane < 8)
        out[(size_t)r * 40 + 32 + lane] = fmaf(dr, a1, bias[32 + lane]);
}

// ----------------------------------------------------------------- host
extern "C" void kernel_launch(void* const* d_in, const int* in_sizes, int n_in,
                              void* d_out, int out_size) {
    const float* x  = (const float*)d_in[0];
    const void*  ei = d_in[1];                 // int32 or int64, detected
    const float* cv = (const float*)d_in[2];
    const float* W1 = (const float*)d_in[3];
    const float* b1 = (const float*)d_in[4];
    const float* W2 = (const float*)d_in[5];
    const float* b2 = (const float*)d_in[6];
    float* out = (float*)d_out;

    int N = in_sizes[0] / 128;
    int E = in_sizes[2];

    static cudaStream_t s1 = nullptr;
    static cudaEvent_t ev_fork = nullptr, ev_side = nullptr;
    if (s1 == nullptr) {
        cudaStreamCreateWithFlags(&s1, cudaStreamNonBlocking);
        cudaEventCreateWithFlags(&ev_fork, cudaEventDisableTiming);
        cudaEventCreateWithFlags(&ev_side, cudaEventDisableTiming);
    }

    int gn = (N + 255) / 256;
    int ge = (E + 255) / 256;
    int gb = (N + 63) / 64;
    int gs = (N + 7) / 8;
    int nbs = (N + SCAN_CHUNK - 1) / SCAN_CHUNK;

    // call 1: W split (main)
    k_wsplit<<<64, 256>>>(W1, W2);

    cudaEventRecord(ev_fork, 0);
    cudaStreamWaitEvent(s1, ev_fork, 0);

    // calls 2,3 on side stream
    k_zero<<<gn, 256, 0, s1>>>(ei, E, N);
    k_cnt <<<ge, 256, 0, s1>>>(ei, E);

    // call 4 (ncu capture slot): GEMM1 on main, y1 = x @ W1^T
    k_gemm_mma<2, 1><<<gb, 256>>>(x, N, 128);

    // rest of side chain
    k_scan1  <<<nbs, 256, 0, s1>>>(N);
    k_scan2  <<<1, 128, 0, s1>>>(nbs, N);
    k_scan3  <<<nbs, 256, 0, s1>>>(N);
    k_scatter<<<ge, 256, 0, s1>>>(ei, cv, E);
    k_rowdeg <<<gs, 256, 0, s1>>>(N);
    cudaEventRecord(ev_side, s1);

    // join, then tail
    cudaStreamWaitEvent(0, ev_side, 0);
    k_spmm128<<<gs, 256>>>(b1, N);
    k_gemm_mma<1, 2><<<gb, 128>>>(nullptr, N, 40);
    k_spmm40<<<gs, 256>>>(b2, out, N);
}

// round 14
// speedup vs baseline: 1.2277x; 1.0402x over previous
#include <cuda_runtime.h>
#include <cuda_bf16.h>

// GCN: out = spmm(w, relu(spmm(w, x@W1^T) + b1) @ W2^T) + b2
// using spmm(h)@W^T == spmm(h@W^T).
//
// Round 14: GEMM operands pre-materialized in m16n8k16 FRAGMENT ORDER in
// gmem (round-13 profile: gemm was L1-bound 55.9% on smem fragment staging,
// tensor only 22%). k_gemm_frag is now pure LDG.128 + HMMA: no smem, no
// syncs, no fragment address math.
//  - k_xsplit: x -> bf16 hi/lo fragments (rg, chunk, lane, areg).
//  - k_wsplit: W1/W2 -> fragment order (64KB/20KB, L2-resident).
//  - k_spmm128 epilogue writes h directly as fragments.
//  - CSR build (raw {col,C}, per-row dinv, norm folded into spmm) forked at
//    t=0 on side stream; gemm1 kept as 4th launch (ncu capture slot).

#define NMAX 100000
#define EMAX 1600000
#define SCAN_CHUNK 1024
#define RGMAX ((NMAX + 15) / 16)          // 6250 row groups

__device__ int   g_is64;
__device__ __align__(16) float g_deg[NMAX];          // dinv after k_rowdeg
__device__ __align__(16) int   g_cnt[NMAX];
__device__ int   g_rowptr[NMAX + 1];
__device__ int   g_cursor[NMAX];
__device__ int   g_bsum[128];
__device__ int   g_boff[128];
__device__ __align__(16) int2  g_cw[EMAX];           // {col, bits(C)}
__device__ __align__(16) float g_y1[(size_t)NMAX * 128];
__device__ __align__(16) float g_y2[(size_t)NMAX * 40];
// fragment arrays: index = ((rg*8 + chunk)*32 + lane)*4 + areg
__device__ __align__(16) unsigned int g_xhf[(size_t)RGMAX * 1024];
__device__ __align__(16) unsigned int g_xlf[(size_t)RGMAX * 1024];
__device__ __align__(16) unsigned int g_hhf[(size_t)RGMAX * 1024];
__device__ __align__(16) unsigned int g_hlf[(size_t)RGMAX * 1024];
// W fragments: index = ((nt*8 + chunk)*32 + lane)*4 + breg
// breg: 0=hi k+0, 1=hi k+8, 2=lo k+0, 3=lo k+8
__device__ __align__(16) unsigned int g_W1f[16 * 8 * 32 * 4];
__device__ __align__(16) unsigned int g_W2f[5 * 8 * 32 * 4];

typedef unsigned int u32;

__device__ __forceinline__ u32 pack2bf(float x, float y) {
    __nv_bfloat162 t = __floats2bfloat162_rn(x, y);
    return *reinterpret_cast<u32*>(&t);
}
__device__ __forceinline__ float bfhi(float x) {
    return __bfloat162float(__float2bfloat16_rn(x));
}
__device__ __forceinline__ void mma_bf16(float* c, u32 a0, u32 a1, u32 a2,
                                         u32 a3, u32 b0, u32 b1) {
    asm("mma.sync.aligned.m16n8k16.row.col.f32.bf16.bf16.f32 "
        "{%0,%1,%2,%3}, {%4,%5,%6,%7}, {%8,%9}, {%0,%1,%2,%3};"
        : "+f"(c[0]), "+f"(c[1]), "+f"(c[2]), "+f"(c[3])
        : "r"(a0), "r"(a1), "r"(a2), "r"(a3), "r"(b0), "r"(b1));
}

__device__ __forceinline__ int edge_at(const void* ei, int E, int part, int e,
                                       int is64) {
    if (is64) return (int)((const long long*)ei)[(size_t)part * E + e];
    return ((const int*)ei)[(size_t)part * E + e];
}

// ------------------------------- x -> bf16 hi/lo fragments (once per call)
__global__ void k_xsplit(const float* __restrict__ x, int N) {
    int i = blockIdx.x * blockDim.x + threadIdx.x;
    int nrg = (N + 15) >> 4;
    if (i >= nrg * 1024) return;
    int areg = i & 3, ln = (i >> 2) & 31, chunk = (i >> 7) & 7, rg = i >> 10;
    int r = rg * 16 + (ln >> 2) + ((areg & 1) ? 8 : 0);
    int k = chunk * 16 + (ln & 3) * 2 + ((areg & 2) ? 8 : 0);
    u32 hi = 0u, lo = 0u;
    if (r < N) {
        float2 v = *(const float2*)&x[(size_t)r * 128 + k];
        hi = pack2bf(v.x, v.y);
        lo = pack2bf(v.x - bfhi(v.x), v.y - bfhi(v.y));
    }
    g_xhf[i] = hi;
    g_xlf[i] = lo;
}

// ------------------------------------ W -> bf16 hi/lo fragments (once)
__global__ void k_wsplit(const float* __restrict__ W1,
                         const float* __restrict__ W2) {
    int i = blockIdx.x * blockDim.x + threadIdx.x;
    if (i < 16 * 8 * 32 * 4) {
        int breg = i & 3, ln = (i >> 2) & 31, chunk = (i >> 7) & 7, nt = i >> 10;
        int c = nt * 8 + (ln >> 2);
        int k = chunk * 16 + (ln & 3) * 2 + ((breg & 1) ? 8 : 0);
        float2 v = *(const float2*)&W1[(size_t)c * 128 + k];
        g_W1f[i] = (breg < 2)
            ? pack2bf(v.x, v.y)
            : pack2bf(v.x - bfhi(v.x), v.y - bfhi(v.y));
    }
    if (i < 5 * 8 * 32 * 4) {
        int breg = i & 3, ln = (i >> 2) & 31, chunk = (i >> 7) & 7, nt = i >> 10;
        int c = nt * 8 + (ln >> 2);
        int k = chunk * 16 + (ln & 3) * 2 + ((breg & 1) ? 8 : 0);
        float2 v = *(const float2*)&W2[(size_t)c * 128 + k];
        g_W2f[i] = (breg < 2)
            ? pack2bf(v.x, v.y)
            : pack2bf(v.x - bfhi(v.x), v.y - bfhi(v.y));
    }
}

// --------------------------------------------- zero counts + dtype detect
__global__ void k_zero(const void* ei, int E, int n) {
    int i = blockIdx.x * blockDim.x + threadIdx.x;
    if (i < n) g_cnt[i] = 0;
    if (i == 0) {
        const long long* p = (const long long*)ei;
        int ok = 1;
        int m = (E < 8) ? E : 8;
        for (int j = 0; j < m; j++) {
            long long v = p[j];
            if (v < 0 || v >= NMAX) ok = 0;
        }
        g_is64 = ok;
    }
}

// --------------------------------------------------------- row counts
__global__ void k_cnt(const void* __restrict__ ei, int E) {
    int e = blockIdx.x * blockDim.x + threadIdx.x;
    if (e >= E) return;
    atomicAdd(&g_cnt[edge_at(ei, E, 0, e, g_is64)], 1);
}

// ------------------------------------- scan pass 1: block sums
__global__ void k_scan1(int n) {
    __shared__ int wsum[8];
    int b = blockIdx.x, t = threadIdx.x;
    int base = b * SCAN_CHUNK + t * 4;
    int4 v = make_int4(0, 0, 0, 0);
    if (base + 3 < n)      v = *(const int4*)&g_cnt[base];
    else if (base < n) {
        v.x = g_cnt[base];
        if (base + 1 < n) v.y = g_cnt[base + 1];
        if (base + 2 < n) v.z = g_cnt[base + 2];
    }
    int s = v.x + v.y + v.z + v.w;
    int lane = t & 31, w = t >> 5;
    int inc = s;
    #pragma unroll
    for (int o = 1; o < 32; o <<= 1) {
        int tv = __shfl_up_sync(0xFFFFFFFFu, inc, o);
        if (lane >= o) inc += tv;
    }
    if (lane == 31) wsum[w] = inc;
    __syncthreads();
    if (t == 0) {
        int tot = 0;
        #pragma unroll
        for (int j = 0; j < 8; j++) tot += wsum[j];
        g_bsum[b] = tot;
    }
}

// ---------------------------- scan pass 2: scan of block sums
__global__ void k_scan2(int nb, int n) {
    __shared__ int wtot[4];
    int t = threadIdx.x;
    int v = (t < nb) ? g_bsum[t] : 0;
    int lane = t & 31, w = t >> 5;
    int inc = v;
    #pragma unroll
    for (int o = 1; o < 32; o <<= 1) {
        int tv = __shfl_up_sync(0xFFFFFFFFu, inc, o);
        if (lane >= o) inc += tv;
    }
    if (lane == 31) wtot[w] = inc;
    __syncthreads();
    int woff = 0;
    #pragma unroll
    for (int j = 0; j < 4; j++) if (j < w) woff += wtot[j];
    int excl = woff + inc - v;
    if (t < nb) g_boff[t] = excl;
    if (t == 127) g_rowptr[n] = woff + inc;
}

// ------------------------- scan pass 3: write rowptr + cursor
__global__ void k_scan3(int n) {
    __shared__ int wsum[8];
    int b = blockIdx.x, t = threadIdx.x;
    int base = b * SCAN_CHUNK + t * 4;
    int4 v = make_int4(0, 0, 0, 0);
    if (base + 3 < n)      v = *(const int4*)&g_cnt[base];
    else if (base < n) {
        v.x = g_cnt[base];
        if (base + 1 < n) v.y = g_cnt[base + 1];
        if (base + 2 < n) v.z = g_cnt[base + 2];
    }
    int s = v.x + v.y + v.z + v.w;
    int lane = t & 31, w = t >> 5;
    int inc = s;
    #pragma unroll
    for (int o = 1; o < 32; o <<= 1) {
        int tv = __shfl_up_sync(0xFFFFFFFFu, inc, o);
        if (lane >= o) inc += tv;
    }
    if (lane == 31) wsum[w] = inc;
    __syncthreads();
    int woff = 0;
    #pragma unroll
    for (int j = 0; j < 8; j++) if (j < w) woff += wsum[j];
    int excl = g_boff[b] + woff + inc - s;
    if (base < n) {
        int p0 = excl, p1 = p0 + v.x, p2 = p1 + v.y, p3 = p2 + v.z;
        g_rowptr[base] = p0;  g_cursor[base] = p0;
        if (base + 1 < n) { g_rowptr[base + 1] = p1; g_cursor[base + 1] = p1; }
        if (base + 2 < n) { g_rowptr[base + 2] = p2; g_cursor[base + 2] = p2; }
        if (base + 3 < n) { g_rowptr[base + 3] = p3; g_cursor[base + 3] = p3; }
    }
}

// ------------------------------------- CSR scatter: raw {col, C}
__global__ void k_scatter(const void* __restrict__ ei,
                          const float* __restrict__ cv, int E) {
    int e = blockIdx.x * blockDim.x + threadIdx.x;
    if (e >= E) return;
    int is64 = g_is64;
    int r = edge_at(ei, E, 0, e, is64);
    int c = edge_at(ei, E, 1, e, is64);
    int pos = atomicAdd(&g_cursor[r], 1);
    g_cw[pos] = make_int2(c, __float_as_int(cv[e]));
}

// --------------------- per-row degree from CSR -> dinv (no atomics)
__global__ void k_rowdeg(int N) {
    int wid = threadIdx.x >> 5, lane = threadIdx.x & 31;
    int r = blockIdx.x * 8 + wid;
    if (r >= N) return;
    int e0 = g_rowptr[r], e1 = g_rowptr[r + 1];
    float s = 0.f;
    for (int e = e0 + lane; e < e1; e += 32) s += __int_as_float(g_cw[e].y);
    #pragma unroll
    for (int o = 16; o > 0; o >>= 1) s += __shfl_xor_sync(0xFFFFFFFFu, s, o);
    if (lane == 0) g_deg[r] = (s > 0.f) ? rsqrtf(s) : 0.f;
}

// --------------------------- fragment GEMM: pure LDG.128 + HMMA
// warp = 16 rows (one rg) x NT*8 cols. Block 256 thr = 8 rgs.
// LAYER 1: A = g_xhf/g_xlf, W = g_W1f, Y = g_y1 (H=128, NT=16).
// LAYER 2: A = g_hhf/g_hlf, W = g_W2f, Y = g_y2 (H=40, NT=5).
template <int NT, int LAYER>
__global__ void k_gemm_frag(int N) {
    int lane = threadIdx.x & 31, w = threadIdx.x >> 5;
    int rg = blockIdx.x * 8 + w;
    int nrg = (N + 15) >> 4;
    if (rg >= nrg) return;

    const u32* Ah = (LAYER == 1) ? g_xhf : g_hhf;
    const u32* Al = (LAYER == 1) ? g_xlf : g_hlf;
    const u32* Wf = (LAYER == 1) ? g_W1f : g_W2f;

    float acc[NT][4];
    #pragma unroll
    for (int nt = 0; nt < NT; nt++)
        #pragma unroll
        for (int q = 0; q < 4; q++) acc[nt][q] = 0.f;

    for (int chunk = 0; chunk < 8; chunk++) {
        int abase = ((rg * 8 + chunk) * 32 + lane) * 4;
        uint4 ah = *(const uint4*)&Ah[abase];
        uint4 al = *(const uint4*)&Al[abase];
        #pragma unroll
        for (int nt = 0; nt < NT; nt++) {
            uint4 b = *(const uint4*)&Wf[((nt * 8 + chunk) * 32 + lane) * 4];
            mma_bf16(acc[nt], ah.x, ah.y, ah.z, ah.w, b.x, b.y);
            mma_bf16(acc[nt], ah.x, ah.y, ah.z, ah.w, b.z, b.w);
            mma_bf16(acc[nt], al.x, al.y, al.z, al.w, b.x, b.y);
        }
    }

    int gid = lane >> 2, tig = lane & 3;
    int r0 = rg * 16 + gid, r1 = r0 + 8;
    float* Y = (LAYER == 1) ? g_y1 : g_y2;
    const int H = (LAYER == 1) ? 128 : 40;
    #pragma unroll
    for (int nt = 0; nt < NT; nt++) {
        int c = nt * 8 + tig * 2;
        if (r0 < N) *(float2*)&Y[(size_t)r0 * H + c] =
            make_float2(acc[nt][0], acc[nt][1]);
        if (r1 < N) *(float2*)&Y[(size_t)r1 * H + c] =
            make_float2(acc[nt][2], acc[nt][3]);
    }
}

// ---- CSR SpMM 128 feats + norm + bias + relu -> h fragments (hi/lo)
__global__ void k_spmm128(const float* __restrict__ bias, int N) {
    int wid = threadIdx.x >> 5, lane = threadIdx.x & 31;
    int r = blockIdx.x * 8 + wid;
    if (r >= N) return;
    const float4* feat = (const float4*)g_y1;
    int e0 = g_rowptr[r], e1 = g_rowptr[r + 1];
    float4 acc = make_float4(0.f, 0.f, 0.f, 0.f);
    for (int e = e0; e < e1; e++) {
        int2 cw = g_cw[e];
        float wv = __int_as_float(cw.y) * g_deg[cw.x];
        float4 v = feat[(size_t)cw.x * 32 + lane];
        acc.x = fmaf(wv, v.x, acc.x);
        acc.y = fmaf(wv, v.y, acc.y);
        acc.z = fmaf(wv, v.z, acc.z);
        acc.w = fmaf(wv, v.w, acc.w);
    }
    float dr = g_deg[r];
    float4 b = ((const float4*)bias)[lane];
    acc.x = fmaxf(fmaf(dr, acc.x, b.x), 0.f);
    acc.y = fmaxf(fmaf(dr, acc.y, b.y), 0.f);
    acc.z = fmaxf(fmaf(dr, acc.z, b.z), 0.f);
    acc.w = fmaxf(fmaf(dr, acc.w, b.w), 0.f);
    // write h directly as m16n8k16 A-fragments (hi/lo)
    int rg = r >> 4, rb = r & 15;
    #pragma unroll
    for (int p = 0; p < 2; p++) {
        int k0 = 4 * lane + 2 * p;
        int chunk = k0 >> 4, kin = k0 & 15;
        int ln = ((rb & 7) << 2) | ((kin & 7) >> 1);
        int areg = ((rb >> 3) & 1) | ((kin & 8) ? 2 : 0);
        int idx = ((rg * 8 + chunk) * 32 + ln) * 4 + areg;
        float fx = p ? acc.z : acc.x;
        float fy = p ? acc.w : acc.y;
        g_hhf[idx] = pack2bf(fx, fy);
        g_hlf[idx] = pack2bf(fx - bfhi(fx), fy - bfhi(fy));
    }
}

// ------------------------- CSR SpMM, 40 feats + norm + bias -> out
__global__ void k_spmm40(const float* __restrict__ bias,
                         float* __restrict__ out, int N) {
    int wid = threadIdx.x >> 5, lane = threadIdx.x & 31;
    int r = blockIdx.x * 8 + wid;
    if (r >= N) return;
    int e0 = g_rowptr[r], e1 = g_rowptr[r + 1];
    float a0 = 0.f, a1 = 0.f;
    for (int e = e0; e < e1; e++) {
        int2 cw = g_cw[e];
        float wv = __int_as_float(cw.y) * g_deg[cw.x];
        const float* f = g_y2 + (size_t)cw.x * 40;
        a0 = fmaf(wv, f[lane], a0);
        if (lane < 8) a1 = fmaf(wv, f[32 + lane], a1);
    }
    float dr = g_deg[r];
    out[(size_t)r * 40 + lane] = fmaf(dr, a0, bias[lane]);
    if (lane < 8)
        out[(size_t)r * 40 + 32 + lane] = fmaf(dr, a1, bias[32 + lane]);
}

// ----------------------------------------------------------------- host
extern "C" void kernel_launch(void* const* d_in, const int* in_sizes, int n_in,
                              void* d_out, int out_size) {
    const float* x  = (const float*)d_in[0];
    const void*  ei = d_in[1];                 // int32 or int64, detected
    const float* cv = (const float*)d_in[2];
    const float* W1 = (const float*)d_in[3];
    const float* b1 = (const float*)d_in[4];
    const float* W2 = (const float*)d_in[5];
    const float* b2 = (const float*)d_in[6];
    float* out = (float*)d_out;

    int N = in_sizes[0] / 128;
    int E = in_sizes[2];

    static cudaStream_t s1 = nullptr;
    static cudaEvent_t ev_fork = nullptr, ev_side = nullptr;
    if (s1 == nullptr) {
        cudaStreamCreateWithFlags(&s1, cudaStreamNonBlocking);
        cudaEventCreateWithFlags(&ev_fork, cudaEventDisableTiming);
        cudaEventCreateWithFlags(&ev_side, cudaEventDisableTiming);
    }

    int gn = (N + 255) / 256;
    int ge = (E + 255) / 256;
    int gs = (N + 7) / 8;
    int nbs = (N + SCAN_CHUNK - 1) / SCAN_CHUNK;
    int nrg = (N + 15) / 16;
    int gfrag = (nrg + 7) / 8;

    // fork side stream at t=0
    cudaEventRecord(ev_fork, 0);
    cudaStreamWaitEvent(s1, ev_fork, 0);

    // main: fragment prep + GEMM1 (gemm1 = 4th kernel launch, ncu slot)
    k_xsplit<<<(nrg * 1024 + 255) / 256, 256>>>(x, N);      // 1
    k_wsplit<<<64, 256>>>(W1, W2);                          // 2
    k_zero<<<gn, 256, 0, s1>>>(ei, E, N);                   // 3 (side)
    k_gemm_frag<16, 1><<<gfrag, 256>>>(N);                  // 4 <- ncu
    // side chain
    k_cnt    <<<ge, 256, 0, s1>>>(ei, E);
    k_scan1  <<<nbs, 256, 0, s1>>>(N);
    k_scan2  <<<1, 128, 0, s1>>>(nbs, N);
    k_scan3  <<<nbs, 256, 0, s1>>>(N);
    k_scatter<<<ge, 256, 0, s1>>>(ei, cv, E);
    k_rowdeg <<<gs, 256, 0, s1>>>(N);
    cudaEventRecord(ev_side, s1);

    // join, then tail
    cudaStreamWaitEvent(0, ev_side, 0);
    k_spmm128<<<gs, 256>>>(b1, N);
    k_gemm_frag<5, 2><<<gfrag, 256>>>(N);
    k_spmm40<<<gs, 256>>>(b2, out, N);
}

// round 15
// speedup vs baseline: 1.4939x; 1.2167x over previous
#include <cuda_runtime.h>
#include <cuda_bf16.h>

// GCN: out = spmm(w, relu(spmm(w, x@W1^T) + b1) @ W2^T) + b2
// using spmm(h)@W^T == spmm(h@W^T).
//
// Round 15:
//  - A-side fragment pre-pass DELETED: m16n8k16 A-fragment addresses are
//    naturally coalesced vs row-major fp32 (4 lanes = 32 contiguous bytes),
//    so the GEMM loads A directly via 4x LDG.64/chunk and does the bf16
//    hi/lo split in registers. x read once (51MB); no g_xhf/g_xlf.
//  - spmm128 writes plain float4 g_h (coalesced); gemm2 direct-loads it.
//  - gemm1: 512-thr blocks, warp = 8 col tiles (2 colgroups), acc 32 regs,
//    __launch_bounds__(512,2) -> ~50% occ (round-14: 100 regs, 23% occ).
//  - side chain: deg folded into count pass, dinv into scan1, full
//    w=dinv*C*dinv into scatter (round-10 form); k_rowdeg dropped.
//  - W fragments (k_wsplit) kept: tiny, L2-resident.

#define NMAX 100000
#define EMAX 1600000
#define SCAN_CHUNK 1024

__device__ int   g_is64;
__device__ __align__(16) float g_deg[NMAX];          // degree -> dinv
__device__ __align__(16) int   g_cnt[NMAX];
__device__ int   g_rowptr[NMAX + 1];
__device__ int   g_cursor[NMAX];
__device__ int   g_bsum[128];
__device__ int   g_boff[128];
__device__ __align__(16) int2  g_cw[EMAX];           // {col, bits(w)}
__device__ __align__(16) float g_y1[(size_t)NMAX * 128];
__device__ __align__(16) float g_h [(size_t)NMAX * 128];
__device__ __align__(16) float g_y2[(size_t)NMAX * 40];
// W fragments: index = ((nt*8 + chunk)*32 + lane)*4 + breg
// breg: 0=hi k+0, 1=hi k+8, 2=lo k+0, 3=lo k+8
__device__ __align__(16) unsigned int g_W1f[16 * 8 * 32 * 4];
__device__ __align__(16) unsigned int g_W2f[5 * 8 * 32 * 4];

typedef unsigned int u32;

__device__ __forceinline__ u32 pack2bf(float x, float y) {
    __nv_bfloat162 t = __floats2bfloat162_rn(x, y);
    return *reinterpret_cast<u32*>(&t);
}
__device__ __forceinline__ float bfhi(float x) {
    return __bfloat162float(__float2bfloat16_rn(x));
}
__device__ __forceinline__ void mma_bf16(float* c, u32 a0, u32 a1, u32 a2,
                                         u32 a3, u32 b0, u32 b1) {
    asm("mma.sync.aligned.m16n8k16.row.col.f32.bf16.bf16.f32 "
        "{%0,%1,%2,%3}, {%4,%5,%6,%7}, {%8,%9}, {%0,%1,%2,%3};"
        : "+f"(c[0]), "+f"(c[1]), "+f"(c[2]), "+f"(c[3])
        : "r"(a0), "r"(a1), "r"(a2), "r"(a3), "r"(b0), "r"(b1));
}

__device__ __forceinline__ int edge_at(const void* ei, int E, int part, int e,
                                       int is64) {
    if (is64) return (int)((const long long*)ei)[(size_t)part * E + e];
    return ((const int*)ei)[(size_t)part * E + e];
}

// ------------------------------------ W -> bf16 hi/lo fragments (once)
__global__ void k_wsplit(const float* __restrict__ W1,
                         const float* __restrict__ W2) {
    int i = blockIdx.x * blockDim.x + threadIdx.x;
    if (i < 16 * 8 * 32 * 4) {
        int breg = i & 3, ln = (i >> 2) & 31, chunk = (i >> 7) & 7, nt = i >> 10;
        int c = nt * 8 + (ln >> 2);
        int k = chunk * 16 + (ln & 3) * 2 + ((breg & 1) ? 8 : 0);
        float2 v = *(const float2*)&W1[(size_t)c * 128 + k];
        g_W1f[i] = (breg < 2)
            ? pack2bf(v.x, v.y)
            : pack2bf(v.x - bfhi(v.x), v.y - bfhi(v.y));
    }
    if (i < 5 * 8 * 32 * 4) {
        int breg = i & 3, ln = (i >> 2) & 31, chunk = (i >> 7) & 7, nt = i >> 10;
        int c = nt * 8 + (ln >> 2);
        int k = chunk * 16 + (ln & 3) * 2 + ((breg & 1) ? 8 : 0);
        float2 v = *(const float2*)&W2[(size_t)c * 128 + k];
        g_W2f[i] = (breg < 2)
            ? pack2bf(v.x, v.y)
            : pack2bf(v.x - bfhi(v.x), v.y - bfhi(v.y));
    }
}

// --------------------------------------------- zero + dtype detect
__global__ void k_zero(const void* ei, int E, int n) {
    int i = blockIdx.x * blockDim.x + threadIdx.x;
    if (i < n) { g_deg[i] = 0.0f; g_cnt[i] = 0; }
    if (i == 0) {
        const long long* p = (const long long*)ei;
        int ok = 1;
        int m = (E < 8) ? E : 8;
        for (int j = 0; j < m; j++) {
            long long v = p[j];
            if (v < 0 || v >= NMAX) ok = 0;
        }
        g_is64 = ok;
    }
}

// --------------------------------------------- row counts + degree
__global__ void k_cntdeg(const void* __restrict__ ei,
                         const float* __restrict__ cv, int E) {
    int e = blockIdx.x * blockDim.x + threadIdx.x;
    if (e >= E) return;
    int r = edge_at(ei, E, 0, e, g_is64);
    atomicAdd(&g_cnt[r], 1);
    atomicAdd(&g_deg[r], cv[e]);
}

// ------------------------- scan pass 1: block sums (+ dinv in place)
__global__ void k_scan1(int n) {
    __shared__ int wsum[8];
    int b = blockIdx.x, t = threadIdx.x;
    int base = b * SCAN_CHUNK + t * 4;
    int4 v = make_int4(0, 0, 0, 0);
    if (base + 3 < n)      v = *(const int4*)&g_cnt[base];
    else if (base < n) {
        v.x = g_cnt[base];
        if (base + 1 < n) v.y = g_cnt[base + 1];
        if (base + 2 < n) v.z = g_cnt[base + 2];
    }
    int s = v.x + v.y + v.z + v.w;
    int lane = t & 31, w = t >> 5;
    int inc = s;
    #pragma unroll
    for (int o = 1; o < 32; o <<= 1) {
        int tv = __shfl_up_sync(0xFFFFFFFFu, inc, o);
        if (lane >= o) inc += tv;
    }
    if (lane == 31) wsum[w] = inc;
    __syncthreads();
    if (t == 0) {
        int tot = 0;
        #pragma unroll
        for (int j = 0; j < 8; j++) tot += wsum[j];
        g_bsum[b] = tot;
    }
    // fused dinv over same range
    if (base + 3 < n) {
        float4 d = *(const float4*)&g_deg[base];
        d.x = (d.x > 0.f) ? rsqrtf(d.x) : 0.f;
        d.y = (d.y > 0.f) ? rsqrtf(d.y) : 0.f;
        d.z = (d.z > 0.f) ? rsqrtf(d.z) : 0.f;
        d.w = (d.w > 0.f) ? rsqrtf(d.w) : 0.f;
        *(float4*)&g_deg[base] = d;
    } else {
        for (int j = 0; j < 4 && base + j < n; j++) {
            float d = g_deg[base + j];
            g_deg[base + j] = (d > 0.f) ? rsqrtf(d) : 0.f;
        }
    }
}

// ---------------------------- scan pass 2: scan of block sums
__global__ void k_scan2(int nb, int n) {
    __shared__ int wtot[4];
    int t = threadIdx.x;
    int v = (t < nb) ? g_bsum[t] : 0;
    int lane = t & 31, w = t >> 5;
    int inc = v;
    #pragma unroll
    for (int o = 1; o < 32; o <<= 1) {
        int tv = __shfl_up_sync(0xFFFFFFFFu, inc, o);
        if (lane >= o) inc += tv;
    }
    if (lane == 31) wtot[w] = inc;
    __syncthreads();
    int woff = 0;
    #pragma unroll
    for (int j = 0; j < 4; j++) if (j < w) woff += wtot[j];
    int excl = woff + inc - v;
    if (t < nb) g_boff[t] = excl;
    if (t == 127) g_rowptr[n] = woff + inc;
}

// ------------------------- scan pass 3: write rowptr + cursor
__global__ void k_scan3(int n) {
    __shared__ int wsum[8];
    int b = blockIdx.x, t = threadIdx.x;
    int base = b * SCAN_CHUNK + t * 4;
    int4 v = make_int4(0, 0, 0, 0);
    if (base + 3 < n)      v = *(const int4*)&g_cnt[base];
    else if (base < n) {
        v.x = g_cnt[base];
        if (base + 1 < n) v.y = g_cnt[base + 1];
        if (base + 2 < n) v.z = g_cnt[base + 2];
    }
    int s = v.x + v.y + v.z + v.w;
    int lane = t & 31, w = t >> 5;
    int inc = s;
    #pragma unroll
    for (int o = 1; o < 32; o <<= 1) {
        int tv = __shfl_up_sync(0xFFFFFFFFu, inc, o);
        if (lane >= o) inc += tv;
    }
    if (lane == 31) wsum[w] = inc;
    __syncthreads();
    int woff = 0;
    #pragma unroll
    for (int j = 0; j < 8; j++) if (j < w) woff += wsum[j];
    int excl = g_boff[b] + woff + inc - s;
    if (base < n) {
        int p0 = excl, p1 = p0 + v.x, p2 = p1 + v.y, p3 = p2 + v.z;
        g_rowptr[base] = p0;  g_cursor[base] = p0;
        if (base + 1 < n) { g_rowptr[base + 1] = p1; g_cursor[base + 1] = p1; }
        if (base + 2 < n) { g_rowptr[base + 2] = p2; g_cursor[base + 2] = p2; }
        if (base + 3 < n) { g_rowptr[base + 3] = p3; g_cursor[base + 3] = p3; }
    }
}

// ----------------------- CSR scatter with full normalized weight
__global__ void k_scatter(const void* __restrict__ ei,
                          const float* __restrict__ cv, int E) {
    int e = blockIdx.x * blockDim.x + threadIdx.x;
    if (e >= E) return;
    int is64 = g_is64;
    int r = edge_at(ei, E, 0, e, is64);
    int c = edge_at(ei, E, 1, e, is64);
    float wv = g_deg[r] * cv[e] * g_deg[c];
    int pos = atomicAdd(&g_cursor[r], 1);
    g_cw[pos] = make_int2(c, __float_as_int(wv));
}

// ---------------- fragment GEMM, A loaded directly from fp32 rows
// A-fragment coalescing: lanes 4j..4j+3 of a warp read 32 contiguous bytes
// of row (rg*16 + j [+8]); bf16 hi/lo split done in registers.
// Warp = 16 rows (one rg) x NT*8 cols (colgroup cg of NCG).
// Block = NCG*8 warps (8 rgs). LAYER 1: A=x, W=g_W1f, Y=g_y1 (H=128).
// LAYER 2: A=g_h, W=g_W2f, Y=g_y2 (H=40).
template <int NT, int NCG, int LAYER>
__global__ void
#if 1
__launch_bounds__(NCG * 256, 2)
#endif
k_gemm_frag(const float* __restrict__ Xin, int N) {
    int lane = threadIdx.x & 31, w = threadIdx.x >> 5;
    int rg = blockIdx.x * 8 + (w & 7);
    int cg = w >> 3;
    int nrg = (N + 15) >> 4;
    if (rg >= nrg) return;

    const float* A = (LAYER == 1) ? Xin : (const float*)g_h;
    const u32*  Wf = (LAYER == 1) ? g_W1f : g_W2f;

    int r0 = rg * 16 + (lane >> 2);
    int k0 = (lane & 3) * 2;
    const float* a0p = A + (size_t)r0 * 128 + k0;
    bool gA0 = (LAYER == 2) || (r0 < N);
    bool gA1 = (LAYER == 2) || (r0 + 8 < N);

    float acc[NT][4];
    #pragma unroll
    for (int nt = 0; nt < NT; nt++)
        #pragma unroll
        for (int q = 0; q < 4; q++) acc[nt][q] = 0.f;

    const float2 z2 = make_float2(0.f, 0.f);
    for (int chunk = 0; chunk < 8; chunk++) {
        int kb = chunk * 16;
        float2 v0 = gA0 ? *(const float2*)(a0p + kb)            : z2;
        float2 v1 = gA1 ? *(const float2*)(a0p + kb + 8 * 128)  : z2;
        float2 v2 = gA0 ? *(const float2*)(a0p + kb + 8)        : z2;
        float2 v3 = gA1 ? *(const float2*)(a0p + kb + 8 * 128 + 8) : z2;
        u32 ah0 = pack2bf(v0.x, v0.y);
        u32 ah1 = pack2bf(v1.x, v1.y);
        u32 ah2 = pack2bf(v2.x, v2.y);
        u32 ah3 = pack2bf(v3.x, v3.y);
        u32 al0 = pack2bf(v0.x - bfhi(v0.x), v0.y - bfhi(v0.y));
        u32 al1 = pack2bf(v1.x - bfhi(v1.x), v1.y - bfhi(v1.y));
        u32 al2 = pack2bf(v2.x - bfhi(v2.x), v2.y - bfhi(v2.y));
        u32 al3 = pack2bf(v3.x - bfhi(v3.x), v3.y - bfhi(v3.y));
        #pragma unroll
        for (int nt = 0; nt < NT; nt++) {
            int ntg = cg * NT + nt;
            uint4 b = *(const uint4*)&Wf[((ntg * 8 + chunk) * 32 + lane) * 4];
            mma_bf16(acc[nt], ah0, ah1, ah2, ah3, b.x, b.y);
            mma_bf16(acc[nt], ah0, ah1, ah2, ah3, b.z, b.w);
            mma_bf16(acc[nt], al0, al1, al2, al3, b.x, b.y);
        }
    }

    int gid = lane >> 2, tig = lane & 3;
    int ro0 = rg * 16 + gid, ro1 = ro0 + 8;
    float* Y = (LAYER == 1) ? g_y1 : g_y2;
    const int H = (LAYER == 1) ? 128 : 40;
    #pragma unroll
    for (int nt = 0; nt < NT; nt++) {
        int c = (cg * NT + nt) * 8 + tig * 2;
        if (ro0 < N) *(float2*)&Y[(size_t)ro0 * H + c] =
            make_float2(acc[nt][0], acc[nt][1]);
        if (ro1 < N) *(float2*)&Y[(size_t)ro1 * H + c] =
            make_float2(acc[nt][2], acc[nt][3]);
    }
}

// ---------- CSR SpMM 128 feats + bias + relu -> g_h (plain float4)
__global__ void k_spmm128(const float* __restrict__ bias, int N) {
    int wid = threadIdx.x >> 5, lane = threadIdx.x & 31;
    int r = blockIdx.x * 8 + wid;
    if (r >= N) return;
    const float4* feat = (const float4*)g_y1;
    int e0 = g_rowptr[r], e1 = g_rowptr[r + 1];
    float4 acc = make_float4(0.f, 0.f, 0.f, 0.f);
    for (int e = e0; e < e1; e++) {
        int2 cw = g_cw[e];
        float wv = __int_as_float(cw.y);
        float4 v = feat[(size_t)cw.x * 32 + lane];
        acc.x = fmaf(wv, v.x, acc.x);
        acc.y = fmaf(wv, v.y, acc.y);
        acc.z = fmaf(wv, v.z, acc.z);
        acc.w = fmaf(wv, v.w, acc.w);
    }
    float4 b = ((const float4*)bias)[lane];
    acc.x = fmaxf(acc.x + b.x, 0.f);
    acc.y = fmaxf(acc.y + b.y, 0.f);
    acc.z = fmaxf(acc.z + b.z, 0.f);
    acc.w = fmaxf(acc.w + b.w, 0.f);
    ((float4*)g_h)[(size_t)r * 32 + lane] = acc;
}

// ------------------------- CSR SpMM, 40 feats + bias -> out
__global__ void k_spmm40(const float* __restrict__ bias,
                         float* __restrict__ out, int N) {
    int wid = threadIdx.x >> 5, lane = threadIdx.x & 31;
    int r = blockIdx.x * 8 + wid;
    if (r >= N) return;
    int e0 = g_rowptr[r], e1 = g_rowptr[r + 1];
    float a0 = 0.f, a1 = 0.f;
    for (int e = e0; e < e1; e++) {
        int2 cw = g_cw[e];
        float wv = __int_as_float(cw.y);
        const float* f = g_y2 + (size_t)cw.x * 40;
        a0 = fmaf(wv, f[lane], a0);
        if (lane < 8) a1 = fmaf(wv, f[32 + lane], a1);
    }
    out[(size_t)r * 40 + lane] = a0 + bias[lane];
    if (lane < 8) out[(size_t)r * 40 + 32 + lane] = a1 + bias[32 + lane];
}

// ----------------------------------------------------------------- host
extern "C" void kernel_launch(void* const* d_in, const int* in_sizes, int n_in,
                              void* d_out, int out_size) {
    const float* x  = (const float*)d_in[0];
    const void*  ei = d_in[1];                 // int32 or int64, detected
    const float* cv = (const float*)d_in[2];
    const float* W1 = (const float*)d_in[3];
    const float* b1 = (const float*)d_in[4];
    const float* W2 = (const float*)d_in[5];
    const float* b2 = (const float*)d_in[6];
    float* out = (float*)d_out;

    int N = in_sizes[0] / 128;
    int E = in_sizes[2];

    static cudaStream_t s1 = nullptr;
    static cudaEvent_t ev_fork = nullptr, ev_side = nullptr;
    if (s1 == nullptr) {
        cudaStreamCreateWithFlags(&s1, cudaStreamNonBlocking);
        cudaEventCreateWithFlags(&ev_fork, cudaEventDisableTiming);
        cudaEventCreateWithFlags(&ev_side, cudaEventDisableTiming);
    }

    int gn = (N + 255) / 256;
    int ge = (E + 255) / 256;
    int gs = (N + 7) / 8;
    int nbs = (N + SCAN_CHUNK - 1) / SCAN_CHUNK;
    int nrg = (N + 15) / 16;
    int gfrag = (nrg + 7) / 8;

    // fork side stream at t=0
    cudaEventRecord(ev_fork, 0);
    cudaStreamWaitEvent(s1, ev_fork, 0);

    k_wsplit<<<64, 256>>>(W1, W2);                          // 1 (main)
    k_zero  <<<gn, 256, 0, s1>>>(ei, E, N);                 // 2 (side)
    k_cntdeg<<<ge, 256, 0, s1>>>(ei, cv, E);                // 3 (side)
    k_gemm_frag<8, 2, 1><<<gfrag, 512>>>(x, N);             // 4 <- ncu slot
    // rest of side chain
    k_scan1  <<<nbs, 256, 0, s1>>>(N);
    k_scan2  <<<1, 128, 0, s1>>>(nbs, N);
    k_scan3  <<<nbs, 256, 0, s1>>>(N);
    k_scatter<<<ge, 256, 0, s1>>>(ei, cv, E);
    cudaEventRecord(ev_side, s1);

    // join, then tail
    cudaStreamWaitEvent(0, ev_side, 0);
    k_spmm128<<<gs, 256>>>(b1, N);
    k_gemm_frag<5, 1, 2><<<gfrag, 256>>>(nullptr, N);
    k_spmm40<<<gs, 256>>>(b2, out, N);
}

// round 16
// speedup vs baseline: 1.6673x; 1.1161x over previous
#include <cuda_runtime.h>
#include <cuda_bf16.h>
#include <cuda_fp16.h>

// GCN: out = spmm(w, relu(spmm(w, x@W1^T) + b1) @ W2^T) + b2
// using spmm(h)@W^T == spmm(h@W^T).
//
// Round 16: fp16 feature matrices for the SpMM gathers.
//   y1 and y2 are stored as __half (written by the GEMM epilogues), halving
//   the dominant L2 gather traffic: spmm128 512->256 B/edge, spmm40
//   160->80 B/edge. W stays bf16 hi/lo split, h stays fp32, accumulation
//   fp32 everywhere -> expected rel_err ~1-4e-4 (threshold 1e-3).
//   Everything else as round 15 (direct-A fragment GEMM, forked CSR build,
//   norm folded into scatter).

#define NMAX 100000
#define EMAX 1600000
#define SCAN_CHUNK 1024

__device__ int   g_is64;
__device__ __align__(16) float g_deg[NMAX];          // degree -> dinv
__device__ __align__(16) int   g_cnt[NMAX];
__device__ int   g_rowptr[NMAX + 1];
__device__ int   g_cursor[NMAX];
__device__ int   g_bsum[128];
__device__ int   g_boff[128];
__device__ __align__(16) int2  g_cw[EMAX];           // {col, bits(w)}
__device__ __align__(16) __half g_y1h[(size_t)NMAX * 128];
__device__ __align__(16) float  g_h [(size_t)NMAX * 128];
__device__ __align__(16) __half g_y2h[(size_t)NMAX * 40];
// W fragments: index = ((nt*8 + chunk)*32 + lane)*4 + breg
// breg: 0=hi k+0, 1=hi k+8, 2=lo k+0, 3=lo k+8
__device__ __align__(16) unsigned int g_W1f[16 * 8 * 32 * 4];
__device__ __align__(16) unsigned int g_W2f[5 * 8 * 32 * 4];

typedef unsigned int u32;

__device__ __forceinline__ u32 pack2bf(float x, float y) {
    __nv_bfloat162 t = __floats2bfloat162_rn(x, y);
    return *reinterpret_cast<u32*>(&t);
}
__device__ __forceinline__ float bfhi(float x) {
    return __bfloat162float(__float2bfloat16_rn(x));
}
__device__ __forceinline__ void mma_bf16(float* c, u32 a0, u32 a1, u32 a2,
                                         u32 a3, u32 b0, u32 b1) {
    asm("mma.sync.aligned.m16n8k16.row.col.f32.bf16.bf16.f32 "
        "{%0,%1,%2,%3}, {%4,%5,%6,%7}, {%8,%9}, {%0,%1,%2,%3};"
        : "+f"(c[0]), "+f"(c[1]), "+f"(c[2]), "+f"(c[3])
        : "r"(a0), "r"(a1), "r"(a2), "r"(a3), "r"(b0), "r"(b1));
}

__device__ __forceinline__ int edge_at(const void* ei, int E, int part, int e,
                                       int is64) {
    if (is64) return (int)((const long long*)ei)[(size_t)part * E + e];
    return ((const int*)ei)[(size_t)part * E + e];
}

// ------------------------------------ W -> bf16 hi/lo fragments (once)
__global__ void k_wsplit(const float* __restrict__ W1,
                         const float* __restrict__ W2) {
    int i = blockIdx.x * blockDim.x + threadIdx.x;
    if (i < 16 * 8 * 32 * 4) {
        int breg = i & 3, ln = (i >> 2) & 31, chunk = (i >> 7) & 7, nt = i >> 10;
        int c = nt * 8 + (ln >> 2);
        int k = chunk * 16 + (ln & 3) * 2 + ((breg & 1) ? 8 : 0);
        float2 v = *(const float2*)&W1[(size_t)c * 128 + k];
        g_W1f[i] = (breg < 2)
            ? pack2bf(v.x, v.y)
            : pack2bf(v.x - bfhi(v.x), v.y - bfhi(v.y));
    }
    if (i < 5 * 8 * 32 * 4) {
        int breg = i & 3, ln = (i >> 2) & 31, chunk = (i >> 7) & 7, nt = i >> 10;
        int c = nt * 8 + (ln >> 2);
        int k = chunk * 16 + (ln & 3) * 2 + ((breg & 1) ? 8 : 0);
        float2 v = *(const float2*)&W2[(size_t)c * 128 + k];
        g_W2f[i] = (breg < 2)
            ? pack2bf(v.x, v.y)
            : pack2bf(v.x - bfhi(v.x), v.y - bfhi(v.y));
    }
}

// --------------------------------------------- zero + dtype detect
__global__ void k_zero(const void* ei, int E, int n) {
    int i = blockIdx.x * blockDim.x + threadIdx.x;
    if (i < n) { g_deg[i] = 0.0f; g_cnt[i] = 0; }
    if (i == 0) {
        const long long* p = (const long long*)ei;
        int ok = 1;
        int m = (E < 8) ? E : 8;
        for (int j = 0; j < m; j++) {
            long long v = p[j];
            if (v < 0 || v >= NMAX) ok = 0;
        }
        g_is64 = ok;
    }
}

// --------------------------------------------- row counts + degree
__global__ void k_cntdeg(const void* __restrict__ ei,
                         const float* __restrict__ cv, int E) {
    int e = blockIdx.x * blockDim.x + threadIdx.x;
    if (e >= E) return;
    int r = edge_at(ei, E, 0, e, g_is64);
    atomicAdd(&g_cnt[r], 1);
    atomicAdd(&g_deg[r], cv[e]);
}

// ------------------------- scan pass 1: block sums (+ dinv in place)
__global__ void k_scan1(int n) {
    __shared__ int wsum[8];
    int b = blockIdx.x, t = threadIdx.x;
    int base = b * SCAN_CHUNK + t * 4;
    int4 v = make_int4(0, 0, 0, 0);
    if (base + 3 < n)      v = *(const int4*)&g_cnt[base];
    else if (base < n) {
        v.x = g_cnt[base];
        if (base + 1 < n) v.y = g_cnt[base + 1];
        if (base + 2 < n) v.z = g_cnt[base + 2];
    }
    int s = v.x + v.y + v.z + v.w;
    int lane = t & 31, w = t >> 5;
    int inc = s;
    #pragma unroll
    for (int o = 1; o < 32; o <<= 1) {
        int tv = __shfl_up_sync(0xFFFFFFFFu, inc, o);
        if (lane >= o) inc += tv;
    }
    if (lane == 31) wsum[w] = inc;
    __syncthreads();
    if (t == 0) {
        int tot = 0;
        #pragma unroll
        for (int j = 0; j < 8; j++) tot += wsum[j];
        g_bsum[b] = tot;
    }
    // fused dinv over same range
    if (base + 3 < n) {
        float4 d = *(const float4*)&g_deg[base];
        d.x = (d.x > 0.f) ? rsqrtf(d.x) : 0.f;
        d.y = (d.y > 0.f) ? rsqrtf(d.y) : 0.f;
        d.z = (d.z > 0.f) ? rsqrtf(d.z) : 0.f;
        d.w = (d.w > 0.f) ? rsqrtf(d.w) : 0.f;
        *(float4*)&g_deg[base] = d;
    } else {
        for (int j = 0; j < 4 && base + j < n; j++) {
            float d = g_deg[base + j];
            g_deg[base + j] = (d > 0.f) ? rsqrtf(d) : 0.f;
        }
    }
}

// ---------------------------- scan pass 2: scan of block sums
__global__ void k_scan2(int nb, int n) {
    __shared__ int wtot[4];
    int t = threadIdx.x;
    int v = (t < nb) ? g_bsum[t] : 0;
    int lane = t & 31, w = t >> 5;
    int inc = v;
    #pragma unroll
    for (int o = 1; o < 32; o <<= 1) {
        int tv = __shfl_up_sync(0xFFFFFFFFu, inc, o);
        if (lane >= o) inc += tv;
    }
    if (lane == 31) wtot[w] = inc;
    __syncthreads();
    int woff = 0;
    #pragma unroll
    for (int j = 0; j < 4; j++) if (j < w) woff += wtot[j];
    int excl = woff + inc - v;
    if (t < nb) g_boff[t] = excl;
    if (t == 127) g_rowptr[n] = woff + inc;
}

// ------------------------- scan pass 3: write rowptr + cursor
__global__ void k_scan3(int n) {
    __shared__ int wsum[8];
    int b = blockIdx.x, t = threadIdx.x;
    int base = b * SCAN_CHUNK + t * 4;
    int4 v = make_int4(0, 0, 0, 0);
    if (base + 3 < n)      v = *(const int4*)&g_cnt[base];
    else if (base < n) {
        v.x = g_cnt[base];
        if (base + 1 < n) v.y = g_cnt[base + 1];
        if (base + 2 < n) v.z = g_cnt[base + 2];
    }
    int s = v.x + v.y + v.z + v.w;
    int lane = t & 31, w = t >> 5;
    int inc = s;
    #pragma unroll
    for (int o = 1; o < 32; o <<= 1) {
        int tv = __shfl_up_sync(0xFFFFFFFFu, inc, o);
        if (lane >= o) inc += tv;
    }
    if (lane == 31) wsum[w] = inc;
    __syncthreads();
    int woff = 0;
    #pragma unroll
    for (int j = 0; j < 8; j++) if (j < w) woff += wsum[j];
    int excl = g_boff[b] + woff + inc - s;
    if (base < n) {
        int p0 = excl, p1 = p0 + v.x, p2 = p1 + v.y, p3 = p2 + v.z;
        g_rowptr[base] = p0;  g_cursor[base] = p0;
        if (base + 1 < n) { g_rowptr[base + 1] = p1; g_cursor[base + 1] = p1; }
        if (base + 2 < n) { g_rowptr[base + 2] = p2; g_cursor[base + 2] = p2; }
        if (base + 3 < n) { g_rowptr[base + 3] = p3; g_cursor[base + 3] = p3; }
    }
}

// ----------------------- CSR scatter with full normalized weight
__global__ void k_scatter(const void* __restrict__ ei,
                          const float* __restrict__ cv, int E) {
    int e = blockIdx.x * blockDim.x + threadIdx.x;
    if (e >= E) return;
    int is64 = g_is64;
    int r = edge_at(ei, E, 0, e, is64);
    int c = edge_at(ei, E, 1, e, is64);
    float wv = g_deg[r] * cv[e] * g_deg[c];
    int pos = atomicAdd(&g_cursor[r], 1);
    g_cw[pos] = make_int2(c, __float_as_int(wv));
}

// ---------------- fragment GEMM, A loaded directly from fp32 rows
// Warp = 16 rows (one rg) x NT*8 cols (colgroup cg of NCG).
// LAYER 1: A=x, W=g_W1f, Y=g_y1h (H=128, fp16 out).
// LAYER 2: A=g_h, W=g_W2f, Y=g_y2h (H=40, fp16 out).
template <int NT, int NCG, int LAYER>
__global__ void __launch_bounds__(NCG * 256, 2)
k_gemm_frag(const float* __restrict__ Xin, int N) {
    int lane = threadIdx.x & 31, w = threadIdx.x >> 5;
    int rg = blockIdx.x * 8 + (w & 7);
    int cg = w >> 3;
    int nrg = (N + 15) >> 4;
    if (rg >= nrg) return;

    const float* A = (LAYER == 1) ? Xin : (const float*)g_h;
    const u32*  Wf = (LAYER == 1) ? g_W1f : g_W2f;

    int r0 = rg * 16 + (lane >> 2);
    int k0 = (lane & 3) * 2;
    const float* a0p = A + (size_t)r0 * 128 + k0;
    bool gA0 = (LAYER == 2) || (r0 < N);
    bool gA1 = (LAYER == 2) || (r0 + 8 < N);

    float acc[NT][4];
    #pragma unroll
    for (int nt = 0; nt < NT; nt++)
        #pragma unroll
        for (int q = 0; q < 4; q++) acc[nt][q] = 0.f;

    const float2 z2 = make_float2(0.f, 0.f);
    for (int chunk = 0; chunk < 8; chunk++) {
        int kb = chunk * 16;
        float2 v0 = gA0 ? *(const float2*)(a0p + kb)            : z2;
        float2 v1 = gA1 ? *(const float2*)(a0p + kb + 8 * 128)  : z2;
        float2 v2 = gA0 ? *(const float2*)(a0p + kb + 8)        : z2;
        float2 v3 = gA1 ? *(const float2*)(a0p + kb + 8 * 128 + 8) : z2;
        u32 ah0 = pack2bf(v0.x, v0.y);
        u32 ah1 = pack2bf(v1.x, v1.y);
        u32 ah2 = pack2bf(v2.x, v2.y);
        u32 ah3 = pack2bf(v3.x, v3.y);
        u32 al0 = pack2bf(v0.x - bfhi(v0.x), v0.y - bfhi(v0.y));
        u32 al1 = pack2bf(v1.x - bfhi(v1.x), v1.y - bfhi(v1.y));
        u32 al2 = pack2bf(v2.x - bfhi(v2.x), v2.y - bfhi(v2.y));
        u32 al3 = pack2bf(v3.x - bfhi(v3.x), v3.y - bfhi(v3.y));
        #pragma unroll
        for (int nt = 0; nt < NT; nt++) {
            int ntg = cg * NT + nt;
            uint4 b = *(const uint4*)&Wf[((ntg * 8 + chunk) * 32 + lane) * 4];
            mma_bf16(acc[nt], ah0, ah1, ah2, ah3, b.x, b.y);
            mma_bf16(acc[nt], ah0, ah1, ah2, ah3, b.z, b.w);
            mma_bf16(acc[nt], al0, al1, al2, al3, b.x, b.y);
        }
    }

    int gid = lane >> 2, tig = lane & 3;
    int ro0 = rg * 16 + gid, ro1 = ro0 + 8;
    __half* Y = (LAYER == 1) ? g_y1h : g_y2h;
    const int H = (LAYER == 1) ? 128 : 40;
    #pragma unroll
    for (int nt = 0; nt < NT; nt++) {
        int c = (cg * NT + nt) * 8 + tig * 2;
        if (ro0 < N) *(__half2*)&Y[(size_t)ro0 * H + c] =
            __floats2half2_rn(acc[nt][0], acc[nt][1]);
        if (ro1 < N) *(__half2*)&Y[(size_t)ro1 * H + c] =
            __floats2half2_rn(acc[nt][2], acc[nt][3]);
    }
}

// ---------- CSR SpMM 128 feats (fp16 gather) + bias + relu -> g_h fp32
__global__ void k_spmm128(const float* __restrict__ bias, int N) {
    int wid = threadIdx.x >> 5, lane = threadIdx.x & 31;
    int r = blockIdx.x * 8 + wid;
    if (r >= N) return;
    const uint2* feat = (const uint2*)g_y1h;   // 4 halfs per lane
    int e0 = g_rowptr[r], e1 = g_rowptr[r + 1];
    float4 acc = make_float4(0.f, 0.f, 0.f, 0.f);
    for (int e = e0; e < e1; e++) {
        int2 cw = g_cw[e];
        float wv = __int_as_float(cw.y);
        uint2 v = feat[(size_t)cw.x * 32 + lane];
        float2 f0 = __half22float2(*(const __half2*)&v.x);
        float2 f1 = __half22float2(*(const __half2*)&v.y);
        acc.x = fmaf(wv, f0.x, acc.x);
        acc.y = fmaf(wv, f0.y, acc.y);
        acc.z = fmaf(wv, f1.x, acc.z);
        acc.w = fmaf(wv, f1.y, acc.w);
    }
    float4 b = ((const float4*)bias)[lane];
    acc.x = fmaxf(acc.x + b.x, 0.f);
    acc.y = fmaxf(acc.y + b.y, 0.f);
    acc.z = fmaxf(acc.z + b.z, 0.f);
    acc.w = fmaxf(acc.w + b.w, 0.f);
    ((float4*)g_h)[(size_t)r * 32 + lane] = acc;
}

// ------------- CSR SpMM, 40 feats (fp16 gather) + bias -> out fp32
// lanes 0..19 each own 2 consecutive feats (one u32 = half2 per edge).
__global__ void k_spmm40(const float* __restrict__ bias,
                         float* __restrict__ out, int N) {
    int wid = threadIdx.x >> 5, lane = threadIdx.x & 31;
    int r = blockIdx.x * 8 + wid;
    if (r >= N) return;
    int e0 = g_rowptr[r], e1 = g_rowptr[r + 1];
    float a0 = 0.f, a1 = 0.f;
    bool act = lane < 20;
    for (int e = e0; e < e1; e++) {
        int2 cw = g_cw[e];
        float wv = __int_as_float(cw.y);
        if (act) {
            const u32* p = (const u32*)(g_y2h + (size_t)cw.x * 40);
            u32 v = p[lane];
            float2 f = __half22float2(*(const __half2*)&v);
            a0 = fmaf(wv, f.x, a0);
            a1 = fmaf(wv, f.y, a1);
        }
    }
    if (act) {
        int c = 2 * lane;
        out[(size_t)r * 40 + c]     = a0 + bias[c];
        out[(size_t)r * 40 + c + 1] = a1 + bias[c + 1];
    }
}

// ----------------------------------------------------------------- host
extern "C" void kernel_launch(void* const* d_in, const int* in_sizes, int n_in,
                              void* d_out, int out_size) {
    const float* x  = (const float*)d_in[0];
    const void*  ei = d_in[1];                 // int32 or int64, detected
    const float* cv = (const float*)d_in[2];
    const float* W1 = (const float*)d_in[3];
    const float* b1 = (const float*)d_in[4];
    const float* W2 = (const float*)d_in[5];
    const float* b2 = (const float*)d_in[6];
    float* out = (float*)d_out;

    int N = in_sizes[0] / 128;
    int E = in_sizes[2];

    static cudaStream_t s1 = nullptr;
    static cudaEvent_t ev_fork = nullptr, ev_side = nullptr;
    if (s1 == nullptr) {
        cudaStreamCreateWithFlags(&s1, cudaStreamNonBlocking);
        cudaEventCreateWithFlags(&ev_fork, cudaEventDisableTiming);
        cudaEventCreateWithFlags(&ev_side, cudaEventDisableTiming);
    }

    int gn = (N + 255) / 256;
    int ge = (E + 255) / 256;
    int gs = (N + 7) / 8;
    int nbs = (N + SCAN_CHUNK - 1) / SCAN_CHUNK;
    int nrg = (N + 15) / 16;
    int gfrag = (nrg + 7) / 8;

    // fork side stream at t=0
    cudaEventRecord(ev_fork, 0);
    cudaStreamWaitEvent(s1, ev_fork, 0);

    k_wsplit<<<64, 256>>>(W1, W2);                          // 1 (main)
    k_zero  <<<gn, 256, 0, s1>>>(ei, E, N);                 // 2 (side)
    k_cntdeg<<<ge, 256, 0, s1>>>(ei, cv, E);                // 3 (side)
    k_gemm_frag<8, 2, 1><<<gfrag, 512>>>(x, N);             // 4 <- ncu slot
    // rest of side chain
    k_scan1  <<<nbs, 256, 0, s1>>>(N);
    k_scan2  <<<1, 128, 0, s1>>>(nbs, N);
    k_scan3  <<<nbs, 256, 0, s1>>>(N);
    k_scatter<<<ge, 256, 0, s1>>>(ei, cv, E);
    cudaEventRecord(ev_side, s1);

    // join, then tail
    cudaStreamWaitEvent(0, ev_side, 0);
    k_spmm128<<<gs, 256>>>(b1, N);
    k_gemm_frag<5, 1, 2><<<gfrag, 256>>>(nullptr, N);
    k_spmm40<<<gs, 256>>>(b2, out, N);
}

// round 17
// speedup vs baseline: 1.7652x; 1.0587x over previous
#include <cuda_runtime.h>
#include <cuda_bf16.h>
#include <cuda_fp16.h>

// GCN: out = spmm(w, relu(spmm(w, x@W1^T) + b1) @ W2^T) + b2
// using spmm(h)@W^T == spmm(h@W^T).
//
// Round 17:
//  - h stored fp16; gemm2 uses f16 MMA directly on h (no A split), W2 as
//    fp16 hi/lo fragments. Halves h write+read traffic.
//  - scatter stores w' = C*dinv[col] only (no dinv[row] gather -> -51MB of
//    sector traffic); SpMMs multiply by dinv[row] once per row.
//  - scan1/2/3 fused into one kernel (98 co-resident blocks, fence+counter+
//    spin; flag reset by k_zero each replay). 11 -> 9 launches.
//  - gemm1 (bf16-split, direct-A) and fp16 y1/y2 gathers unchanged.

#define NMAX 100000
#define EMAX 1600000
#define SCAN_CHUNK 1024

__device__ int   g_is64;
__device__ int   g_scan_done;
__device__ int   g_scan_flag;
__device__ __align__(16) float g_deg[NMAX];          // degree -> dinv
__device__ __align__(16) int   g_cnt[NMAX];
__device__ int   g_rowptr[NMAX + 1];
__device__ int   g_cursor[NMAX];
__device__ int   g_bsum[128];
__device__ int   g_boff[128];
__device__ __align__(16) int2  g_cw[EMAX];           // {col, bits(C*dinv[col])}
__device__ __align__(16) __half g_y1h[(size_t)NMAX * 128];
__device__ __align__(16) __half g_h [(size_t)NMAX * 128];
__device__ __align__(16) __half g_y2h[(size_t)NMAX * 40];
// W1 fragments (bf16): index = ((nt*8 + chunk)*32 + lane)*4 + breg
// breg: 0=hi k+0, 1=hi k+8, 2=lo k+0, 3=lo k+8
__device__ __align__(16) unsigned int g_W1f[16 * 8 * 32 * 4];
// W2 fragments (fp16 hi/lo), same layout
__device__ __align__(16) unsigned int g_W2f[5 * 8 * 32 * 4];

typedef unsigned int u32;

__device__ __forceinline__ u32 pack2bf(float x, float y) {
    __nv_bfloat162 t = __floats2bfloat162_rn(x, y);
    return *reinterpret_cast<u32*>(&t);
}
__device__ __forceinline__ u32 pack2hf(float x, float y) {
    __half2 t = __floats2half2_rn(x, y);
    return *reinterpret_cast<u32*>(&t);
}
__device__ __forceinline__ float bfhi(float x) {
    return __bfloat162float(__float2bfloat16_rn(x));
}
__device__ __forceinline__ float hfhi(float x) {
    return __half2float(__float2half_rn(x));
}
__device__ __forceinline__ void mma_bf16(float* c, u32 a0, u32 a1, u32 a2,
                                         u32 a3, u32 b0, u32 b1) {
    asm("mma.sync.aligned.m16n8k16.row.col.f32.bf16.bf16.f32 "
        "{%0,%1,%2,%3}, {%4,%5,%6,%7}, {%8,%9}, {%0,%1,%2,%3};"
        : "+f"(c[0]), "+f"(c[1]), "+f"(c[2]), "+f"(c[3])
        : "r"(a0), "r"(a1), "r"(a2), "r"(a3), "r"(b0), "r"(b1));
}
__device__ __forceinline__ void mma_f16(float* c, u32 a0, u32 a1, u32 a2,
                                        u32 a3, u32 b0, u32 b1) {
    asm("mma.sync.aligned.m16n8k16.row.col.f32.f16.f16.f32 "
        "{%0,%1,%2,%3}, {%4,%5,%6,%7}, {%8,%9}, {%0,%1,%2,%3};"
        : "+f"(c[0]), "+f"(c[1]), "+f"(c[2]), "+f"(c[3])
        : "r"(a0), "r"(a1), "r"(a2), "r"(a3), "r"(b0), "r"(b1));
}

__device__ __forceinline__ int edge_at(const void* ei, int E, int part, int e,
                                       int is64) {
    if (is64) return (int)((const long long*)ei)[(size_t)part * E + e];
    return ((const int*)ei)[(size_t)part * E + e];
}

// ------------------- W1 -> bf16 hi/lo, W2 -> fp16 hi/lo fragments (once)
__global__ void k_wsplit(const float* __restrict__ W1,
                         const float* __restrict__ W2) {
    int i = blockIdx.x * blockDim.x + threadIdx.x;
    if (i < 16 * 8 * 32 * 4) {
        int breg = i & 3, ln = (i >> 2) & 31, chunk = (i >> 7) & 7, nt = i >> 10;
        int c = nt * 8 + (ln >> 2);
        int k = chunk * 16 + (ln & 3) * 2 + ((breg & 1) ? 8 : 0);
        float2 v = *(const float2*)&W1[(size_t)c * 128 + k];
        g_W1f[i] = (breg < 2)
            ? pack2bf(v.x, v.y)
            : pack2bf(v.x - bfhi(v.x), v.y - bfhi(v.y));
    }
    if (i < 5 * 8 * 32 * 4) {
        int breg = i & 3, ln = (i >> 2) & 31, chunk = (i >> 7) & 7, nt = i >> 10;
        int c = nt * 8 + (ln >> 2);
        int k = chunk * 16 + (ln & 3) * 2 + ((breg & 1) ? 8 : 0);
        float2 v = *(const float2*)&W2[(size_t)c * 128 + k];
        g_W2f[i] = (breg < 2)
            ? pack2hf(v.x, v.y)
            : pack2hf(v.x - hfhi(v.x), v.y - hfhi(v.y));
    }
}

// --------------------------------------------- zero + dtype detect + flags
__global__ void k_zero(const void* ei, int E, int n) {
    int i = blockIdx.x * blockDim.x + threadIdx.x;
    if (i < n) { g_deg[i] = 0.0f; g_cnt[i] = 0; }
    if (i == 0) {
        const long long* p = (const long long*)ei;
        int ok = 1;
        int m = (E < 8) ? E : 8;
        for (int j = 0; j < m; j++) {
            long long v = p[j];
            if (v < 0 || v >= NMAX) ok = 0;
        }
        g_is64 = ok;
        g_scan_done = 0;
        g_scan_flag = 0;
    }
}

// --------------------------------------------- row counts + degree
__global__ void k_cntdeg(const void* __restrict__ ei,
                         const float* __restrict__ cv, int E) {
    int e = blockIdx.x * blockDim.x + threadIdx.x;
    if (e >= E) return;
    int r = edge_at(ei, E, 0, e, g_is64);
    atomicAdd(&g_cnt[r], 1);
    atomicAdd(&g_deg[r], cv[e]);
}

// ------------- fused scan (one launch): block sums + dinv | last-block
// scans sums | all blocks write rowptr/cursor. Requires all blocks resident
// (nbs <= 128 < 148 SMs) -> spin is deadlock-free.
__global__ void k_scanf(int n) {
    __shared__ int wsum[8];
    __shared__ int wtot[4];
    __shared__ int am_last;
    int b = blockIdx.x, t = threadIdx.x;
    int base = b * SCAN_CHUNK + t * 4;

    // ---- phase 1: local scan + block sum (+ dinv fuse)
    int4 v = make_int4(0, 0, 0, 0);
    if (base + 3 < n)      v = *(const int4*)&g_cnt[base];
    else if (base < n) {
        v.x = g_cnt[base];
        if (base + 1 < n) v.y = g_cnt[base + 1];
        if (base + 2 < n) v.z = g_cnt[base + 2];
    }
    int s = v.x + v.y + v.z + v.w;
    int lane = t & 31, w = t >> 5;
    int inc = s;
    #pragma unroll
    for (int o = 1; o < 32; o <<= 1) {
        int tv = __shfl_up_sync(0xFFFFFFFFu, inc, o);
        if (lane >= o) inc += tv;
    }
    if (lane == 31) wsum[w] = inc;
    __syncthreads();
    if (t == 0) {
        int tot = 0;
        #pragma unroll
        for (int j = 0; j < 8; j++) tot += wsum[j];
        g_bsum[b] = tot;
    }
    // dinv over same range (independent of scan)
    if (base + 3 < n) {
        float4 d = *(const float4*)&g_deg[base];
        d.x = (d.x > 0.f) ? rsqrtf(d.x) : 0.f;
        d.y = (d.y > 0.f) ? rsqrtf(d.y) : 0.f;
        d.z = (d.z > 0.f) ? rsqrtf(d.z) : 0.f;
        d.w = (d.w > 0.f) ? rsqrtf(d.w) : 0.f;
        *(float4*)&g_deg[base] = d;
    } else {
        for (int j = 0; j < 4 && base + j < n; j++) {
            float d = g_deg[base + j];
            g_deg[base + j] = (d > 0.f) ? rsqrtf(d) : 0.f;
        }
    }

    // ---- arrive; last block scans the block sums
    if (t == 0) {
        __threadfence();
        int prev = atomicAdd(&g_scan_done, 1);
        am_last = (prev == (int)gridDim.x - 1);
    }
    __syncthreads();
    if (am_last) {
        int nb = gridDim.x;
        if (t < 128) {
            int vv = (t < nb) ? g_bsum[t] : 0;
            int inc2 = vv;
            #pragma unroll
            for (int o = 1; o < 32; o <<= 1) {
                int tv = __shfl_up_sync(0xFFFFFFFFu, inc2, o);
                if (lane >= o) inc2 += tv;
            }
            if (lane == 31) wtot[t >> 5] = inc2;
        }
        __syncthreads();
        if (t < 128) {
            int woff2 = 0;
            #pragma unroll
            for (int j = 0; j < 4; j++) if (j < (t >> 5)) woff2 += wtot[j];
            // recompute inc2 is gone; redo cheap:
            int vv = (t < nb) ? g_bsum[t] : 0;
            int inc2 = vv;
            #pragma unroll
            for (int o = 1; o < 32; o <<= 1) {
                int tv = __shfl_up_sync(0xFFFFFFFFu, inc2, o);
                if (lane >= o) inc2 += tv;
            }
            int excl2 = woff2 + inc2 - vv;
            if (t < nb) g_boff[t] = excl2;
            if (t == 127) g_rowptr[n] = woff2 + inc2;
        }
        __syncthreads();
        if (t == 0) {
            __threadfence();
            atomicExch(&g_scan_flag, 1);
        }
    }
    if (t == 0) {
        while (atomicAdd(&g_scan_flag, 0) == 0) __nanosleep(64);
    }
    __syncthreads();

    // ---- phase 3: write rowptr + cursor (reuse phase-1 inc/s/wsum)
    int woff = 0;
    #pragma unroll
    for (int j = 0; j < 8; j++) if (j < w) woff += wsum[j];
    int excl = g_boff[b] + woff + inc - s;
    if (base < n) {
        int p0 = excl, p1 = p0 + v.x, p2 = p1 + v.y, p3 = p2 + v.z;
        g_rowptr[base] = p0;  g_cursor[base] = p0;
        if (base + 1 < n) { g_rowptr[base + 1] = p1; g_cursor[base + 1] = p1; }
        if (base + 2 < n) { g_rowptr[base + 2] = p2; g_cursor[base + 2] = p2; }
        if (base + 3 < n) { g_rowptr[base + 3] = p3; g_cursor[base + 3] = p3; }
    }
}

// ---------------- CSR scatter: w' = C * dinv[col] (dinv[row] deferred)
__global__ void k_scatter(const void* __restrict__ ei,
                          const float* __restrict__ cv, int E) {
    int e = blockIdx.x * blockDim.x + threadIdx.x;
    if (e >= E) return;
    int is64 = g_is64;
    int r = edge_at(ei, E, 0, e, is64);
    int c = edge_at(ei, E, 1, e, is64);
    float wv = cv[e] * g_deg[c];
    int pos = atomicAdd(&g_cursor[r], 1);
    g_cw[pos] = make_int2(c, __float_as_int(wv));
}

// ---------------- GEMM1: A from fp32 x (bf16 split in regs), Y = y1h fp16
// Warp = 16 rows (one rg) x 8 col tiles (colgroup cg of 2). Block 512 thr.
__global__ void __launch_bounds__(512, 2)
k_gemm1(const float* __restrict__ Xin, int N) {
    int lane = threadIdx.x & 31, w = threadIdx.x >> 5;
    int rg = blockIdx.x * 8 + (w & 7);
    int cg = w >> 3;
    int nrg = (N + 15) >> 4;
    if (rg >= nrg) return;

    int r0 = rg * 16 + (lane >> 2);
    int k0 = (lane & 3) * 2;
    const float* a0p = Xin + (size_t)r0 * 128 + k0;
    bool gA0 = (r0 < N);
    bool gA1 = (r0 + 8 < N);

    float acc[8][4];
    #pragma unroll
    for (int nt = 0; nt < 8; nt++)
        #pragma unroll
        for (int q = 0; q < 4; q++) acc[nt][q] = 0.f;

    const float2 z2 = make_float2(0.f, 0.f);
    for (int chunk = 0; chunk < 8; chunk++) {
        int kb = chunk * 16;
        float2 v0 = gA0 ? *(const float2*)(a0p + kb)               : z2;
        float2 v1 = gA1 ? *(const float2*)(a0p + kb + 8 * 128)     : z2;
        float2 v2 = gA0 ? *(const float2*)(a0p + kb + 8)           : z2;
        float2 v3 = gA1 ? *(const float2*)(a0p + kb + 8 * 128 + 8) : z2;
        u32 ah0 = pack2bf(v0.x, v0.y);
        u32 ah1 = pack2bf(v1.x, v1.y);
        u32 ah2 = pack2bf(v2.x, v2.y);
        u32 ah3 = pack2bf(v3.x, v3.y);
        u32 al0 = pack2bf(v0.x - bfhi(v0.x), v0.y - bfhi(v0.y));
        u32 al1 = pack2bf(v1.x - bfhi(v1.x), v1.y - bfhi(v1.y));
        u32 al2 = pack2bf(v2.x - bfhi(v2.x), v2.y - bfhi(v2.y));
        u32 al3 = pack2bf(v3.x - bfhi(v3.x), v3.y - bfhi(v3.y));
        #pragma unroll
        for (int nt = 0; nt < 8; nt++) {
            int ntg = cg * 8 + nt;
            uint4 b = *(const uint4*)&g_W1f[((ntg * 8 + chunk) * 32 + lane) * 4];
            mma_bf16(acc[nt], ah0, ah1, ah2, ah3, b.x, b.y);
            mma_bf16(acc[nt], ah0, ah1, ah2, ah3, b.z, b.w);
            mma_bf16(acc[nt], al0, al1, al2, al3, b.x, b.y);
        }
    }

    int gid = lane >> 2, tig = lane & 3;
    int ro0 = rg * 16 + gid, ro1 = ro0 + 8;
    #pragma unroll
    for (int nt = 0; nt < 8; nt++) {
        int c = (cg * 8 + nt) * 8 + tig * 2;
        if (ro0 < N) *(__half2*)&g_y1h[(size_t)ro0 * 128 + c] =
            __floats2half2_rn(acc[nt][0], acc[nt][1]);
        if (ro1 < N) *(__half2*)&g_y1h[(size_t)ro1 * 128 + c] =
            __floats2half2_rn(acc[nt][2], acc[nt][3]);
    }
}

// ---------------- GEMM2: A = h fp16 (direct), W2 fp16 hi/lo, Y = y2h
// Warp = 16 rows x 5 tiles (40 cols). Block 256 thr = 8 rgs.
__global__ void k_gemm2(int N) {
    int lane = threadIdx.x & 31, w = threadIdx.x >> 5;
    int rg = blockIdx.x * 8 + w;
    int nrg = (N + 15) >> 4;
    if (rg >= nrg) return;

    int r0 = rg * 16 + (lane >> 2);
    int k0 = (lane & 3) * 2;
    const __half* pr0 = g_h + (size_t)r0 * 128 + k0;
    const __half* pr1 = pr0 + 8 * 128;

    float acc[5][4];
    #pragma unroll
    for (int nt = 0; nt < 5; nt++)
        #pragma unroll
        for (int q = 0; q < 4; q++) acc[nt][q] = 0.f;

    for (int chunk = 0; chunk < 8; chunk++) {
        int kb = chunk * 16;
        u32 a0 = *(const u32*)(pr0 + kb);
        u32 a1 = *(const u32*)(pr1 + kb);
        u32 a2 = *(const u32*)(pr0 + kb + 8);
        u32 a3 = *(const u32*)(pr1 + kb + 8);
        #pragma unroll
        for (int nt = 0; nt < 5; nt++) {
            uint4 b = *(const uint4*)&g_W2f[((nt * 8 + chunk) * 32 + lane) * 4];
            mma_f16(acc[nt], a0, a1, a2, a3, b.x, b.y);
            mma_f16(acc[nt], a0, a1, a2, a3, b.z, b.w);
        }
    }

    int gid = lane >> 2, tig = lane & 3;
    int ro0 = rg * 16 + gid, ro1 = ro0 + 8;
    #pragma unroll
    for (int nt = 0; nt < 5; nt++) {
        int c = nt * 8 + tig * 2;
        if (ro0 < N) *(__half2*)&g_y2h[(size_t)ro0 * 40 + c] =
            __floats2half2_rn(acc[nt][0], acc[nt][1]);
        if (ro1 < N) *(__half2*)&g_y2h[(size_t)ro1 * 40 + c] =
            __floats2half2_rn(acc[nt][2], acc[nt][3]);
    }
}

// ------- CSR SpMM 128 feats (fp16 gather) + dr + bias + relu -> h fp16
__global__ void k_spmm128(const float* __restrict__ bias, int N) {
    int wid = threadIdx.x >> 5, lane = threadIdx.x & 31;
    int r = blockIdx.x * 8 + wid;
    if (r >= N) return;
    const uint2* feat = (const uint2*)g_y1h;   // 4 halfs per lane
    int e0 = g_rowptr[r], e1 = g_rowptr[r + 1];
    float4 acc = make_float4(0.f, 0.f, 0.f, 0.f);
    for (int e = e0; e < e1; e++) {
        int2 cw = g_cw[e];
        float wv = __int_as_float(cw.y);
        uint2 v = feat[(size_t)cw.x * 32 + lane];
        float2 f0 = __half22float2(*(const __half2*)&v.x);
        float2 f1 = __half22float2(*(const __half2*)&v.y);
        acc.x = fmaf(wv, f0.x, acc.x);
        acc.y = fmaf(wv, f0.y, acc.y);
        acc.z = fmaf(wv, f1.x, acc.z);
        acc.w = fmaf(wv, f1.y, acc.w);
    }
    float dr = g_deg[r];
    float4 b = ((const float4*)bias)[lane];
    acc.x = fmaxf(fmaf(dr, acc.x, b.x), 0.f);
    acc.y = fmaxf(fmaf(dr, acc.y, b.y), 0.f);
    acc.z = fmaxf(fmaf(dr, acc.z, b.z), 0.f);
    acc.w = fmaxf(fmaf(dr, acc.w, b.w), 0.f);
    uint2 hv;
    hv.x = pack2hf(acc.x, acc.y);
    hv.y = pack2hf(acc.z, acc.w);
    ((uint2*)g_h)[(size_t)r * 32 + lane] = hv;
}

// ------- CSR SpMM, 40 feats (fp16 gather) + dr + bias -> out fp32
__global__ void k_spmm40(const float* __restrict__ bias,
                         float* __restrict__ out, int N) {
    int wid = threadIdx.x >> 5, lane = threadIdx.x & 31;
    int r = blockIdx.x * 8 + wid;
    if (r >= N) return;
    int e0 = g_rowptr[r], e1 = g_rowptr[r + 1];
    float a0 = 0.f, a1 = 0.f;
    bool act = lane < 20;
    for (int e = e0; e < e1; e++) {
        int2 cw = g_cw[e];
        float wv = __int_as_float(cw.y);
        if (act) {
            const u32* p = (const u32*)(g_y2h + (size_t)cw.x * 40);
            u32 v = p[lane];
            float2 f = __half22float2(*(const __half2*)&v);
            a0 = fmaf(wv, f.x, a0);
            a1 = fmaf(wv, f.y, a1);
        }
    }
    if (act) {
        float dr = g_deg[r];
        int c = 2 * lane;
        out[(size_t)r * 40 + c]     = fmaf(dr, a0, bias[c]);
        out[(size_t)r * 40 + c + 1] = fmaf(dr, a1, bias[c + 1]);
    }
}

// ----------------------------------------------------------------- host
extern "C" void kernel_launch(void* const* d_in, const int* in_sizes, int n_in,
                              void* d_out, int out_size) {
    const float* x  = (const float*)d_in[0];
    const void*  ei = d_in[1];                 // int32 or int64, detected
    const float* cv = (const float*)d_in[2];
    const float* W1 = (const float*)d_in[3];
    const float* b1 = (const float*)d_in[4];
    const float* W2 = (const float*)d_in[5];
    const float* b2 = (const float*)d_in[6];
    float* out = (float*)d_out;

    int N = in_sizes[0] / 128;
    int E = in_sizes[2];

    static cudaStream_t s1 = nullptr;
    static cudaEvent_t ev_fork = nullptr, ev_side = nullptr;
    if (s1 == nullptr) {
        cudaStreamCreateWithFlags(&s1, cudaStreamNonBlocking);
        cudaEventCreateWithFlags(&ev_fork, cudaEventDisableTiming);
        cudaEventCreateWithFlags(&ev_side, cudaEventDisableTiming);
    }

    int gn = (N + 255) / 256;
    int ge = (E + 255) / 256;
    int gs = (N + 7) / 8;
    int nbs = (N + SCAN_CHUNK - 1) / SCAN_CHUNK;
    int nrg = (N + 15) / 16;
    int gfrag = (nrg + 7) / 8;

    // fork side stream at t=0
    cudaEventRecord(ev_fork, 0);
    cudaStreamWaitEvent(s1, ev_fork, 0);

    k_wsplit<<<64, 256>>>(W1, W2);                          // 1 (main)
    k_zero  <<<gn, 256, 0, s1>>>(ei, E, N);                 // 2 (side)
    k_cntdeg<<<ge, 256, 0, s1>>>(ei, cv, E);                // 3 (side)
    k_gemm1 <<<gfrag, 512>>>(x, N);                         // 4 <- ncu slot
    // rest of side chain
    k_scanf  <<<nbs, 256, 0, s1>>>(N);
    k_scatter<<<ge, 256, 0, s1>>>(ei, cv, E);
    cudaEventRecord(ev_side, s1);

    // join, then tail
    cudaStreamWaitEvent(0, ev_side, 0);
    k_spmm128<<<gs, 256>>>(b1, N);
    k_gemm2<<<gfrag, 256>>>(N);
    k_spmm40<<<gs, 256>>>(b2, out, N);
}